// round 12
// baseline (speedup 1.0000x reference)
#include <cuda_runtime.h>
#include <cuda_bf16.h>
#include <math.h>
#include <stdint.h>

#define HW 65536
#define BATCH 4
#define NSEG 32
#define GCH 128
#define GPAD 140

// ---------------- static scratch ----------------
__device__ float g_qkv [(size_t)BATCH * 288 * HW];   // qkv pre-dwconv; later gated FFN 'g'
__device__ float g_qkvd[(size_t)BATCH * 288 * HW];   // qkv post-dwconv (q|k|v)
__device__ float g_svpq[(size_t)BATCH * 12  * HW];   // svp_q
__device__ float g_mu  [(size_t)BATCH * HW];
__device__ float g_rs  [(size_t)BATCH * HW];
__device__ float g_ss  [BATCH * 204];
__device__ float g_gp  [NSEG * 16 * 648];
__device__ __nv_bfloat16 g_Mh [BATCH * 96 * 96];
__device__ __nv_bfloat16 g_Ml [BATCH * 96 * 96];
__device__ __nv_bfloat16 g_Aqh[288 * 96];
__device__ __nv_bfloat16 g_Aql[288 * 96];
__device__ float g_bq  [288];
__device__ __nv_bfloat16 g_Agh[512 * 96];
__device__ __nv_bfloat16 g_Agl[512 * 96];
__device__ float g_bg  [512];
__device__ __nv_bfloat16 g_Fh [96 * 256];
__device__ __nv_bfloat16 g_Fl [96 * 256];

// ---------------- helpers ----------------
__device__ __forceinline__ void bsplit(float v, __nv_bfloat16& h, __nv_bfloat16& l) {
    h = __float2bfloat16(v);
    l = __float2bfloat16(v - __bfloat162float(h));
}
__device__ __forceinline__ void split2(float a, float b, uint32_t& h, uint32_t& l) {
    __nv_bfloat16 ha = __float2bfloat16(a), hb = __float2bfloat16(b);
    __nv_bfloat16 la = __float2bfloat16(a - __bfloat162float(ha));
    __nv_bfloat16 lb = __float2bfloat16(b - __bfloat162float(hb));
    __nv_bfloat162 hv(ha, hb), lv(la, lb);
    h = *(uint32_t*)&hv; l = *(uint32_t*)&lv;
}
__device__ __forceinline__ uint32_t s2u(const void* p) {
    return (uint32_t)__cvta_generic_to_shared(p);
}
__device__ __forceinline__ void ldsm4t(uint32_t* r, uint32_t addr) {
    asm volatile("ldmatrix.sync.aligned.m8n8.x4.trans.shared.b16 {%0,%1,%2,%3}, [%4];"
        : "=r"(r[0]), "=r"(r[1]), "=r"(r[2]), "=r"(r[3]) : "r"(addr));
}
__device__ __forceinline__ void mma_bf16(float* d, const uint32_t* a, const uint32_t* b) {
    asm volatile("mma.sync.aligned.m16n8k16.row.col.f32.bf16.bf16.f32 "
        "{%0,%1,%2,%3}, {%4,%5,%6,%7}, {%8,%9}, {%0,%1,%2,%3};"
        : "+f"(d[0]), "+f"(d[1]), "+f"(d[2]), "+f"(d[3])
        : "r"(a[0]), "r"(a[1]), "r"(a[2]), "r"(a[3]), "r"(b[0]), "r"(b[1]));
}
__device__ __forceinline__ float gatef(float a, float bb) {
    float sig = 1.f / (1.f + expf(-bb));
    float gel = 0.5f * a * (1.f + erff(a * 0.70710678118654752f));
    return a * sig + bb * gel;
}

// ---------------- prep: fold LN weights, split to bf16 hi/lo, zero ss ----------------
__global__ void prep_kernel(const float* __restrict__ qkv_w,
                            const float* __restrict__ n1w, const float* __restrict__ n1b,
                            const float* __restrict__ ffn1_w, const float* __restrict__ ffn2_w,
                            const float* __restrict__ n2w, const float* __restrict__ n2b,
                            const float* __restrict__ ffn_out_w, float* __restrict__ ss) {
    int r = blockIdx.x;
    int k = threadIdx.x;  // 0..95
    __shared__ float red[96];
    if (r < 288) {
        float wv = qkv_w[r * 96 + k];
        bsplit(wv * n1w[k], g_Aqh[r * 96 + k], g_Aql[r * 96 + k]);
        red[k] = wv * n1b[k];
        __syncthreads();
        if (k == 0) { float s = 0.f; for (int j = 0; j < 96; j++) s += red[j]; g_bq[r] = s; }
    } else if (r < 800) {
        int c = r - 288;                  // 0..511
        int T = c >> 4, wi = c & 15;
        int g = T * 8 + (wi & 7);
        bool valid = (g < 255);
        const float* W = (wi < 8) ? ffn1_w : ffn2_w;
        float wv = valid ? W[g * 96 + k] : 0.f;
        bsplit(wv * n2w[k], g_Agh[c * 96 + k], g_Agl[c * 96 + k]);
        red[k] = wv * n2b[k];
        __syncthreads();
        if (k == 0) {
            float s = 0.f; for (int j = 0; j < 96; j++) s += red[j];
            if (valid) g_bg[(wi < 8 ? 0 : 256) + g] = s;
        }
    } else if (r < 896) {
        int o = r - 800;                  // 0..95
        for (int kk = k; kk < 256; kk += 96) {
            float v = (kk < 255) ? ffn_out_w[o * 255 + kk] : 0.f;
            bsplit(v, g_Fh[o * 256 + kk], g_Fl[o * 256 + kk]);
        }
    } else {
        for (int j = k; j < BATCH * 204; j += 96) ss[j] = 0.f;
    }
}

// ---------------- LN stats (LN1 only; LN2 fused into gemm epilogue) ----------------
__global__ void ln_stats(const float* __restrict__ x, float* __restrict__ mu,
                         float* __restrict__ rs) {
    int i = blockIdx.x * blockDim.x + threadIdx.x;
    if (i >= BATCH * HW) return;
    int b = i >> 16, pix = i & 65535;
    const float* xp = x + (long long)b * 96 * HW + pix;
    float sum = 0.f, sq = 0.f;
    #pragma unroll 8
    for (int c = 0; c < 96; c++) {
        float v = xp[(long long)c * HW];
        sum += v; sq += v * v;
    }
    float m = sum * (1.f / 96.f);
    float var = sq * (1.f / 96.f) - m * m;
    mu[i] = m;
    rs[i] = rsqrtf(var + 1e-5f);
}

// ---------------- tensor-core GEMM: C[M,65536]=A[M,K]@B, split-bf16 ----------------
// BM=BN=128, BK=32, 256 threads (4x2 warps of 32x64). k-major smem, trans ldmatrix.
// GRID: blockIdx.x = m-tile (FASTEST -> sibling CTAs share B n-slice in L2),
//       blockIdx.y = n-slice, blockIdx.z = batch.
// EPI: 0 plain(+RESID), 1 +bias, 2 dual-gate. STATS: fused LN stats (gridDim.x==1, M=96).
template <int EPI, int LN, int RESID, int STATS>
__global__ __launch_bounds__(256) void gemm_t(
    const __nv_bfloat16* __restrict__ Ah, const __nv_bfloat16* __restrict__ Al,
    const float* __restrict__ B, const float* __restrict__ R, float* __restrict__ C,
    const float* __restrict__ bias,
    const float* __restrict__ mu, const float* __restrict__ rs,
    float* __restrict__ muo, float* __restrict__ rso,
    int M, int K, int Kpad,
    long long sA, long long sB, long long sR, long long sC)
{
    extern __shared__ __align__(16) char smem_raw[];
    __nv_bfloat16* Ash = (__nv_bfloat16*)smem_raw;       // [2][32][136]
    __nv_bfloat16* Asl = Ash + 2 * 4352;
    __nv_bfloat16* Bsh = Asl + 2 * 4352;
    __nv_bfloat16* Bsl = Bsh + 2 * 4352;

    Ah += (long long)blockIdx.z * sA;
    Al += (long long)blockIdx.z * sA;
    B  += (long long)blockIdx.z * sB;
    C  += (long long)blockIdx.z * sC;
    if (RESID) R += (long long)blockIdx.z * sR;
    if (LN) { mu += (long long)blockIdx.z * HW; rs += (long long)blockIdx.z * HW; }

    const int m_base = blockIdx.x * 128;
    const int n_base = blockIdx.y * 128;
    const int tid  = threadIdx.x;
    const int lane = tid & 31;
    const int warp = tid >> 5;
    const int wm = warp >> 1, wn = warp & 1;

    // loader coords
    const int bcol = (tid & 31) * 4;   // B col (fixed)
    const int bk0  = tid >> 5;         // B k row base (+8j)
    const int am0  = (tid & 63) * 2;   // A m pair base (even)
    const int akc  = tid >> 6;         // A k-chunk (0..3), 8 k each

    float4 m4, r4;
    if (LN) {
        m4 = *(const float4*)(mu + n_base + bcol);
        r4 = *(const float4*)(rs + n_base + bcol);
    }

    float acc[2][8][4];
    #pragma unroll
    for (int i = 0; i < 2; i++)
        #pragma unroll
        for (int j = 0; j < 8; j++)
            #pragma unroll
            for (int q = 0; q < 4; q++) acc[i][j][q] = 0.f;

    const int nst = (K + 31) >> 5;
    uint4 rgah[2], rgal[2];            // rows am0, am0+1
    float4 rgb[4];

    // ldmatrix lane-derived offsets
    const int a_row = (lane & 7) + ((lane >> 4) & 1) * 8;
    const int a_col = ((lane >> 3) & 1) * 8;
    const int b_row = (lane & 7) + ((lane >> 3) & 1) * 8;
    const int b_col = ((lane >> 4) & 1) * 8 + wn * 64;

    auto fetch = [&](int kg) {
        int g0 = m_base + am0;
        long long o0 = (long long)g0 * Kpad + kg + akc * 8;
        if (g0 < M) {
            rgah[0] = *(const uint4*)(Ah + o0);
            rgal[0] = *(const uint4*)(Al + o0);
        } else {
            rgah[0] = make_uint4(0, 0, 0, 0);
            rgal[0] = make_uint4(0, 0, 0, 0);
        }
        if (g0 + 1 < M) {
            rgah[1] = *(const uint4*)(Ah + o0 + Kpad);
            rgal[1] = *(const uint4*)(Al + o0 + Kpad);
        } else {
            rgah[1] = make_uint4(0, 0, 0, 0);
            rgal[1] = make_uint4(0, 0, 0, 0);
        }
        #pragma unroll
        for (int j = 0; j < 4; j++) {
            int kb = kg + bk0 + 8 * j;
            if (kb < K) {
                float4 v = *(const float4*)(B + (long long)kb * HW + n_base + bcol);
                if (LN) {
                    v.x = (v.x - m4.x) * r4.x; v.y = (v.y - m4.y) * r4.y;
                    v.z = (v.z - m4.z) * r4.z; v.w = (v.w - m4.w) * r4.w;
                }
                rgb[j] = v;
            } else {
                rgb[j] = make_float4(0.f, 0.f, 0.f, 0.f);
            }
        }
    };
    auto stash = [&](int buf) {
        int base = buf * 4352;
        const uint32_t* h0 = (const uint32_t*)&rgah[0];
        const uint32_t* h1 = (const uint32_t*)&rgah[1];
        const uint32_t* l0 = (const uint32_t*)&rgal[0];
        const uint32_t* l1 = (const uint32_t*)&rgal[1];
        #pragma unroll
        for (int r = 0; r < 4; r++) {
            int k0 = akc * 8 + r * 2;
            *(uint32_t*)&Ash[base + k0 * 136 + am0]       = __byte_perm(h0[r], h1[r], 0x5410);
            *(uint32_t*)&Ash[base + (k0 + 1) * 136 + am0] = __byte_perm(h0[r], h1[r], 0x7632);
            *(uint32_t*)&Asl[base + k0 * 136 + am0]       = __byte_perm(l0[r], l1[r], 0x5410);
            *(uint32_t*)&Asl[base + (k0 + 1) * 136 + am0] = __byte_perm(l0[r], l1[r], 0x7632);
        }
        #pragma unroll
        for (int j = 0; j < 4; j++) {
            int kb = bk0 + 8 * j;
            uint2 h2, l2;
            split2(rgb[j].x, rgb[j].y, h2.x, l2.x);
            split2(rgb[j].z, rgb[j].w, h2.y, l2.y);
            *(uint2*)&Bsh[base + kb * 136 + bcol] = h2;
            *(uint2*)&Bsl[base + kb * 136 + bcol] = l2;
        }
    };

    fetch(0);
    stash(0);
    __syncthreads();

    for (int s = 0; s < nst; s++) {
        int buf = s & 1;
        if (s + 1 < nst) fetch((s + 1) * 32);

        int base = buf * 4352;
        #pragma unroll
        for (int step = 0; step < 2; step++) {
            int k0 = step * 16;
            uint32_t ah[2][4], al[2][4];
            #pragma unroll
            for (int i = 0; i < 2; i++) {
                int col = wm * 32 + i * 16 + a_col;
                int off = base + (k0 + a_row) * 136 + col;
                ldsm4t(ah[i], s2u(&Ash[off]));
                ldsm4t(al[i], s2u(&Asl[off]));
            }
            uint32_t bh[4][4], bl[4][4];
            #pragma unroll
            for (int jp = 0; jp < 4; jp++) {
                int col = b_col + jp * 16;
                int off = base + (k0 + b_row) * 136 + col;
                ldsm4t(bh[jp], s2u(&Bsh[off]));
                ldsm4t(bl[jp], s2u(&Bsl[off]));
            }
            #pragma unroll
            for (int i = 0; i < 2; i++) {
                #pragma unroll
                for (int j = 0; j < 8; j++) {
                    int jp = j >> 1;
                    const uint32_t* bhp = (j & 1) ? bh[jp] + 2 : bh[jp];
                    const uint32_t* blp = (j & 1) ? bl[jp] + 2 : bl[jp];
                    mma_bf16(acc[i][j], ah[i], bhp);
                    mma_bf16(acc[i][j], ah[i], blp);
                    mma_bf16(acc[i][j], al[i], bhp);
                }
            }
        }
        if (s + 1 < nst) stash(buf ^ 1);
        __syncthreads();
    }

    // ---------------- epilogue ----------------
    float ls[16], ls2[16];
    if (STATS) {
        #pragma unroll
        for (int e = 0; e < 16; e++) { ls[e] = 0.f; ls2[e] = 0.f; }
    }

    if (EPI == 2) {
        #pragma unroll
        for (int i = 0; i < 2; i++) {
            int T = (m_base >> 4) + wm * 2 + i;
            int g = T * 8 + (lane >> 2);
            if (g < 255) {
                float b1 = bias[g], b2 = bias[256 + g];
                #pragma unroll
                for (int j = 0; j < 8; j++) {
                    int col = n_base + wn * 64 + j * 8 + 2 * (lane & 3);
                    float2 v;
                    v.x = gatef(acc[i][j][0] + b1, acc[i][j][2] + b2);
                    v.y = gatef(acc[i][j][1] + b1, acc[i][j][3] + b2);
                    *(float2*)(C + (long long)g * HW + col) = v;
                }
            }
        }
    } else {
        #pragma unroll
        for (int i = 0; i < 2; i++) {
            int r0 = m_base + wm * 32 + i * 16 + (lane >> 2);
            int r1 = r0 + 8;
            float bv0 = 0.f, bv1 = 0.f;
            if (EPI == 1) {
                if (r0 < M) bv0 = bias[r0];
                if (r1 < M) bv1 = bias[r1];
            }
            #pragma unroll
            for (int j = 0; j < 8; j++) {
                int col = n_base + wn * 64 + j * 8 + 2 * (lane & 3);
                if (r0 < M) {
                    float2 v = make_float2(acc[i][j][0] + bv0, acc[i][j][1] + bv0);
                    long long o = (long long)r0 * HW + col;
                    if (RESID) { float2 rr = *(const float2*)(R + o); v.x += rr.x; v.y += rr.y; }
                    *(float2*)(C + o) = v;
                    if (STATS) {
                        ls[2 * j] += v.x; ls[2 * j + 1] += v.y;
                        ls2[2 * j] += v.x * v.x; ls2[2 * j + 1] += v.y * v.y;
                    }
                }
                if (r1 < M) {
                    float2 v = make_float2(acc[i][j][2] + bv1, acc[i][j][3] + bv1);
                    long long o = (long long)r1 * HW + col;
                    if (RESID) { float2 rr = *(const float2*)(R + o); v.x += rr.x; v.y += rr.y; }
                    *(float2*)(C + o) = v;
                    if (STATS) {
                        ls[2 * j] += v.x; ls[2 * j + 1] += v.y;
                        ls2[2 * j] += v.x * v.x; ls2[2 * j + 1] += v.y * v.y;
                    }
                }
            }
        }
    }

    if (STATS) {
        __syncthreads();
        float* sstat = (float*)smem_raw;   // [0..127]=sum, [128..255]=sumsq
        sstat[tid] = 0.f;
        __syncthreads();
        if (wm < 3) {   // M=96: only warps wm 0..2 hold valid rows
            #pragma unroll
            for (int o = 16; o >= 4; o >>= 1) {
                #pragma unroll
                for (int e = 0; e < 16; e++) {
                    ls[e]  += __shfl_down_sync(0xffffffffu, ls[e],  o);
                    ls2[e] += __shfl_down_sync(0xffffffffu, ls2[e], o);
                }
            }
            if (lane < 4) {
                #pragma unroll
                for (int e = 0; e < 16; e++) {
                    int j = e >> 1, q = e & 1;
                    int nl = wn * 64 + j * 8 + 2 * lane + q;
                    atomicAdd(&sstat[nl], ls[e]);
                    atomicAdd(&sstat[128 + nl], ls2[e]);
                }
            }
        }
        __syncthreads();
        if (tid < 128) {
            float sm = sstat[tid] * (1.f / 96.f);
            float sq = sstat[tid + 128] * (1.f / 96.f);
            float var = sq - sm * sm;
            muo[(long long)blockIdx.z * HW + n_base + tid] = sm;
            rso[(long long)blockIdx.z * HW + n_base + tid] = rsqrtf(var + 1e-5f);
        }
    }
}

// ---------------- 3x3 depthwise conv: 32x32 tile, float4 I/O ----------------
__global__ __launch_bounds__(256) void dwconv3(const float* __restrict__ in,
                                               const float* __restrict__ w,
                                               float* __restrict__ out) {
    int zc = blockIdx.z;
    int c = zc % 288;
    const float* src = in  + (long long)zc * HW;
    float*       dst = out + (long long)zc * HW;
    int ox = blockIdx.x * 32, oy = blockIdx.y * 32;
    __shared__ float s[34][40];    // col c <-> gx = ox-4+c ; needed cols 3..36
    int tid = threadIdx.x;
    #pragma unroll
    for (int j = 0; j < 2; j++) {
        int sl = tid + j * 256;
        if (sl < 340) {
            int r = sl / 10, q = sl - r * 10;
            int gy = oy + r - 1, gx = ox - 4 + q * 4;
            float4 v = make_float4(0.f, 0.f, 0.f, 0.f);
            if (gy >= 0 && gy < 256 && gx >= 0 && gx <= 252)
                v = *(const float4*)(src + gy * 256 + gx);
            *(float4*)&s[r][q * 4] = v;
        }
    }
    __syncthreads();
    const float* wc = w + c * 9;
    float w00 = wc[0], w01 = wc[1], w02 = wc[2];
    float w10 = wc[3], w11 = wc[4], w12 = wc[5];
    float w20 = wc[6], w21 = wc[7], w22 = wc[8];
    int row  = tid >> 3;           // 0..31
    int colq = (tid & 7) * 4;      // 0..28
    float v[3][6];
    #pragma unroll
    for (int dr = 0; dr < 3; dr++) {
        float4 m = *(const float4*)&s[row + dr][colq + 4];
        v[dr][0] = s[row + dr][colq + 3];
        v[dr][1] = m.x; v[dr][2] = m.y; v[dr][3] = m.z; v[dr][4] = m.w;
        v[dr][5] = s[row + dr][colq + 8];
    }
    float4 o;
    float* op = (float*)&o;
    #pragma unroll
    for (int t = 0; t < 4; t++) {
        op[t] = w00 * v[0][t] + w01 * v[0][t + 1] + w02 * v[0][t + 2]
              + w10 * v[1][t] + w11 * v[1][t + 1] + w12 * v[1][t + 2]
              + w20 * v[2][t] + w21 * v[2][t + 1] + w22 * v[2][t + 2];
    }
    *(float4*)(dst + (oy + row) * 256 + ox + colq) = o;
}

// ---------------- svp 1x1 conv ----------------
__global__ void svp_kernel(const float* __restrict__ fea, const float* __restrict__ w,
                           float* __restrict__ out) {
    int i = blockIdx.x * blockDim.x + threadIdx.x;
    if (i >= BATCH * HW) return;
    int b = i >> 16, pix = i & 65535;
    const float* f = fea + (long long)b * 3 * HW + pix;
    float f0 = f[0], f1 = f[HW], f2 = f[2 * HW];
    float* o = out + (long long)b * 12 * HW + pix;
    #pragma unroll
    for (int r = 0; r < 12; r++)
        o[(long long)r * HW] = w[r * 3] * f0 + w[r * 3 + 1] * f1 + w[r * 3 + 2] * f2;
}

// ---------------- Gram partials + fused per-row sum of squares ----------------
__global__ __launch_bounds__(672) void gram_kernel(const float* __restrict__ qkvd,
                                                   const float* __restrict__ svpq,
                                                   float* __restrict__ gp,
                                                   float* __restrict__ ss) {
    __shared__ float qs[27 * GPAD];
    __shared__ float ks[24 * GPAD];
    __shared__ float red_s[51];
    int seg = blockIdx.x;
    int bh  = blockIdx.y;
    int b = bh >> 2, h = bh & 3;
    int tid = threadIdx.x;
    int c = tid / 24, d = tid % 24;
    bool active = tid < 648;
    long long segoff = (long long)seg * (HW / NSEG);
    float acc = 0.f;
    float sqacc[3] = {0.f, 0.f, 0.f};
    if (tid < 51) red_s[tid] = 0.f;

    for (int ch = 0; ch < HW / NSEG; ch += GCH) {
        int jj = 0;
        for (int i = tid; i < 51 * (GCH / 4); i += 672, jj++) {
            int row = i / (GCH / 4), col4 = i % (GCH / 4);
            const float* src;
            float* dstb;
            if (row < 27) {
                src = (row < 24) ? qkvd + ((long long)b * 288 + h * 24 + row) * HW
                                 : svpq + ((long long)b * 12 + h * 3 + (row - 24)) * HW;
                dstb = qs + row * GPAD;
            } else {
                int rr = row - 27;
                src = qkvd + ((long long)b * 288 + 96 + h * 24 + rr) * HW;
                dstb = ks + rr * GPAD;
            }
            float4 v = *(const float4*)(src + segoff + ch + col4 * 4);
            *(float4*)(dstb + col4 * 4) = v;
            sqacc[jj] += v.x * v.x + v.y * v.y + v.z * v.z + v.w * v.w;
        }
        __syncthreads();
        if (active) {
            const float4* q4 = (const float4*)(qs + c * GPAD);
            const float4* k4 = (const float4*)(ks + d * GPAD);
            #pragma unroll 8
            for (int p = 0; p < GCH / 4; p++) {
                float4 qv = q4[p], kv = k4[p];
                acc += qv.x * kv.x + qv.y * kv.y + qv.z * kv.z + qv.w * kv.w;
            }
        }
        __syncthreads();
    }
    if (active) gp[((long long)seg * 16 + bh) * 648 + tid] = acc;

    // flush fused sumsq
    {
        int jj = 0;
        for (int i = tid; i < 51 * (GCH / 4); i += 672, jj++) {
            int row = i / (GCH / 4);
            atomicAdd(&red_s[row], sqacc[jj]);
        }
    }
    __syncthreads();
    if (tid < 51) {
        int row = tid;
        int idx;
        if (row < 24)       idx = b * 204 + h * 24 + row;
        else if (row < 27)  idx = b * 204 + 192 + h * 3 + (row - 24);
        else                idx = b * 204 + 96 + h * 24 + (row - 27);
        atomicAdd(&ss[idx], red_s[row]);
    }
}

// ---------------- attn softmax + fold proj_out -> M[b] (bf16 split) ----------------
__global__ void attnm_kernel(const float* __restrict__ gp, const float* __restrict__ ss,
                             const float* __restrict__ temp, const float* __restrict__ projw,
                             __nv_bfloat16* __restrict__ Mh, __nv_bfloat16* __restrict__ Ml) {
    int b = blockIdx.x;
    __shared__ float attn_s[4][27][24];
    int tid = threadIdx.x;
    if (tid < 108) {
        int h = tid / 27, c = tid % 27;
        float ssq = (c < 24) ? ss[b * 204 + h * 24 + c]
                             : ss[b * 204 + 192 + h * 3 + (c - 24)];
        float nq = fmaxf(sqrtf(ssq), 1e-12f);
        float t = temp[h];
        float row[24];
        #pragma unroll
        for (int d = 0; d < 24; d++) {
            float g = 0.f;
            for (int s = 0; s < NSEG; s++)
                g += gp[((long long)s * 16 + b * 4 + h) * 648 + c * 24 + d];
            float nk = fmaxf(sqrtf(ss[b * 204 + 96 + h * 24 + d]), 1e-12f);
            row[d] = g * t / (nq * nk);
        }
        float mx = row[0];
        #pragma unroll
        for (int d = 1; d < 24; d++) mx = fmaxf(mx, row[d]);
        float sum = 0.f;
        #pragma unroll
        for (int d = 0; d < 24; d++) { row[d] = expf(row[d] - mx); sum += row[d]; }
        float inv = 1.f / sum;
        #pragma unroll
        for (int d = 0; d < 24; d++) attn_s[h][c][d] = row[d] * inv;
    }
    __syncthreads();
    for (int e = tid; e < 96 * 96; e += blockDim.x) {
        int o = e / 96, col = e % 96;
        int h = col / 24, d = col % 24;
        float s = 0.f;
        #pragma unroll
        for (int c = 0; c < 27; c++)
            s += projw[o * 108 + h * 27 + c] * attn_s[h][c][d];
        bsplit(s, Mh[b * 9216 + e], Ml[b * 9216 + e]);
    }
}

// ---------------- launch ----------------
extern "C" void kernel_launch(void* const* d_in, const int* in_sizes, int n_in,
                              void* d_out, int out_size) {
    const float* x           = (const float*)d_in[0];
    const float* svp_fea     = (const float*)d_in[1];
    const float* n1w         = (const float*)d_in[2];
    const float* n1b         = (const float*)d_in[3];
    const float* qkv_w       = (const float*)d_in[4];
    const float* qkv_dw_w    = (const float*)d_in[5];
    const float* svp_w       = (const float*)d_in[6];
    const float* temperature = (const float*)d_in[7];
    const float* proj_out_w  = (const float*)d_in[8];
    const float* n2w         = (const float*)d_in[9];
    const float* n2b         = (const float*)d_in[10];
    const float* ffn1_w      = (const float*)d_in[11];
    const float* ffn2_w      = (const float*)d_in[12];
    const float* ffn_out_w   = (const float*)d_in[13];
    float* out = (float*)d_out;

    float *qkv, *qkvd, *svpq, *mu, *rs, *ss, *gp, *bq, *bg;
    __nv_bfloat16 *Mh, *Ml, *Aqh, *Aql, *Agh, *Agl, *Fh, *Fl;
    cudaGetSymbolAddress((void**)&qkv,  g_qkv);
    cudaGetSymbolAddress((void**)&qkvd, g_qkvd);
    cudaGetSymbolAddress((void**)&svpq, g_svpq);
    cudaGetSymbolAddress((void**)&mu,   g_mu);
    cudaGetSymbolAddress((void**)&rs,   g_rs);
    cudaGetSymbolAddress((void**)&ss,   g_ss);
    cudaGetSymbolAddress((void**)&gp,   g_gp);
    cudaGetSymbolAddress((void**)&Mh,   g_Mh);
    cudaGetSymbolAddress((void**)&Ml,   g_Ml);
    cudaGetSymbolAddress((void**)&Aqh,  g_Aqh);
    cudaGetSymbolAddress((void**)&Aql,  g_Aql);
    cudaGetSymbolAddress((void**)&bq,   g_bq);
    cudaGetSymbolAddress((void**)&Agh,  g_Agh);
    cudaGetSymbolAddress((void**)&Agl,  g_Agl);
    cudaGetSymbolAddress((void**)&bg,   g_bg);
    cudaGetSymbolAddress((void**)&Fh,   g_Fh);
    cudaGetSymbolAddress((void**)&Fl,   g_Fl);

    const int GEMM_SMEM = 4 * 2 * 32 * 136 * 2;   // 69632 bytes
    cudaFuncSetAttribute(gemm_t<1, 1, 0, 0>, cudaFuncAttributeMaxDynamicSharedMemorySize, GEMM_SMEM);
    cudaFuncSetAttribute(gemm_t<0, 0, 1, 1>, cudaFuncAttributeMaxDynamicSharedMemorySize, GEMM_SMEM);
    cudaFuncSetAttribute(gemm_t<2, 1, 0, 0>, cudaFuncAttributeMaxDynamicSharedMemorySize, GEMM_SMEM);
    cudaFuncSetAttribute(gemm_t<0, 0, 1, 0>, cudaFuncAttributeMaxDynamicSharedMemorySize, GEMM_SMEM);

    const int pixBlocks = (BATCH * HW + 255) / 256;

    // 0. fold LN weights into split-bf16 A matrices; zero ss
    prep_kernel<<<897, 96>>>(qkv_w, n1w, n1b, ffn1_w, ffn2_w, n2w, n2b, ffn_out_w, ss);
    // 1. LN1 stats
    ln_stats<<<pixBlocks, 256>>>(x, mu, rs);
    // 2. qkv = Aq @ LN(x) + bq   (m-tiles fastest -> B shared in L2)
    gemm_t<1, 1, 0, 0><<<dim3(3, 512, BATCH), 256, GEMM_SMEM>>>(Aqh, Aql, x, nullptr, qkv,
        bq, mu, rs, nullptr, nullptr, 288, 96, 96, 0, 96LL * HW, 0, 288LL * HW);
    // 3. depthwise 3x3
    dwconv3<<<dim3(8, 8, BATCH * 288), 256>>>(qkv, qkv_dw_w, qkvd);
    // 4. svp_q
    svp_kernel<<<pixBlocks, 256>>>(svp_fea, svp_w, svpq);
    // 5. Gram partials + fused sumsq
    gram_kernel<<<dim3(NSEG, 16), 672>>>(qkvd, svpq, gp, ss);
    // 6. softmax + fold proj_out -> M[b]
    attnm_kernel<<<BATCH, 128>>>(gp, ss, temperature, proj_out_w, Mh, Ml);
    // 7. x2 = x + M_b @ v -> out, fused LN2 stats
    gemm_t<0, 0, 1, 1><<<dim3(1, 512, BATCH), 256, GEMM_SMEM>>>(Mh, Ml, qkvd + 192LL * HW, x, out,
        nullptr, nullptr, nullptr, mu, rs, 96, 96, 96, 9216, 288LL * HW, 96LL * HW, 96LL * HW);
    // 8. interleaved ffn1/ffn2 GEMM + fused dual-gate -> g (qkv buffer)
    gemm_t<2, 1, 0, 0><<<dim3(4, 512, BATCH), 256, GEMM_SMEM>>>(Agh, Agl, out, nullptr, qkv,
        bg, mu, rs, nullptr, nullptr, 512, 96, 96, 0, 96LL * HW, 0, 288LL * HW);
    // 9. out = out + ffn_out_w @ g
    gemm_t<0, 0, 1, 0><<<dim3(1, 512, BATCH), 256, GEMM_SMEM>>>(Fh, Fl, qkv, out, out,
        nullptr, nullptr, nullptr, nullptr, nullptr, 96, 255, 256, 0, 288LL * HW, 96LL * HW, 96LL * HW);
}

// round 13
// speedup vs baseline: 1.1413x; 1.1413x over previous
#include <cuda_runtime.h>
#include <cuda_bf16.h>
#include <math.h>
#include <stdint.h>

#define HW 65536
#define BATCH 4
#define NSEG 32
#define GCH 128
#define GPAD 140

// ---------------- static scratch ----------------
__device__ float g_qkv [(size_t)BATCH * 288 * HW];   // qkv pre-dwconv; later gated FFN 'g'
__device__ float g_qkvd[(size_t)BATCH * 288 * HW];   // qkv post-dwconv (q|k|v)
__device__ float g_svpq[(size_t)BATCH * 12  * HW];   // svp_q
__device__ float g_mu  [(size_t)BATCH * HW];
__device__ float g_rs  [(size_t)BATCH * HW];
__device__ float g_ss  [BATCH * 204];
__device__ float g_gp  [NSEG * 16 * 648];
__device__ __nv_bfloat16 g_Mh [BATCH * 96 * 96];
__device__ __nv_bfloat16 g_Ml [BATCH * 96 * 96];
__device__ __nv_bfloat16 g_Aqh[288 * 96];
__device__ __nv_bfloat16 g_Aql[288 * 96];
__device__ float g_bq  [288];
__device__ __nv_bfloat16 g_Agh[512 * 96];
__device__ __nv_bfloat16 g_Agl[512 * 96];
__device__ float g_bg  [512];
__device__ __nv_bfloat16 g_Fh [96 * 256];
__device__ __nv_bfloat16 g_Fl [96 * 256];

// ---------------- helpers ----------------
__device__ __forceinline__ void bsplit(float v, __nv_bfloat16& h, __nv_bfloat16& l) {
    h = __float2bfloat16(v);
    l = __float2bfloat16(v - __bfloat162float(h));
}
__device__ __forceinline__ void split2(float a, float b, uint32_t& h, uint32_t& l) {
    __nv_bfloat16 ha = __float2bfloat16(a), hb = __float2bfloat16(b);
    __nv_bfloat16 la = __float2bfloat16(a - __bfloat162float(ha));
    __nv_bfloat16 lb = __float2bfloat16(b - __bfloat162float(hb));
    __nv_bfloat162 hv(ha, hb), lv(la, lb);
    h = *(uint32_t*)&hv; l = *(uint32_t*)&lv;
}
__device__ __forceinline__ uint32_t s2u(const void* p) {
    return (uint32_t)__cvta_generic_to_shared(p);
}
__device__ __forceinline__ void ldsm4t(uint32_t* r, uint32_t addr) {
    asm volatile("ldmatrix.sync.aligned.m8n8.x4.trans.shared.b16 {%0,%1,%2,%3}, [%4];"
        : "=r"(r[0]), "=r"(r[1]), "=r"(r[2]), "=r"(r[3]) : "r"(addr));
}
__device__ __forceinline__ void mma_bf16(float* d, const uint32_t* a, const uint32_t* b) {
    asm volatile("mma.sync.aligned.m16n8k16.row.col.f32.bf16.bf16.f32 "
        "{%0,%1,%2,%3}, {%4,%5,%6,%7}, {%8,%9}, {%0,%1,%2,%3};"
        : "+f"(d[0]), "+f"(d[1]), "+f"(d[2]), "+f"(d[3])
        : "r"(a[0]), "r"(a[1]), "r"(a[2]), "r"(a[3]), "r"(b[0]), "r"(b[1]));
}
__device__ __forceinline__ float gatef(float a, float bb) {
    float sig = 1.f / (1.f + expf(-bb));
    float gel = 0.5f * a * (1.f + erff(a * 0.70710678118654752f));
    return a * sig + bb * gel;
}

// ---------------- prep: fold LN weights, split to bf16 hi/lo, zero ss ----------------
__global__ void prep_kernel(const float* __restrict__ qkv_w,
                            const float* __restrict__ n1w, const float* __restrict__ n1b,
                            const float* __restrict__ ffn1_w, const float* __restrict__ ffn2_w,
                            const float* __restrict__ n2w, const float* __restrict__ n2b,
                            const float* __restrict__ ffn_out_w, float* __restrict__ ss) {
    int r = blockIdx.x;
    int k = threadIdx.x;  // 0..95
    __shared__ float red[96];
    if (r < 288) {
        float wv = qkv_w[r * 96 + k];
        bsplit(wv * n1w[k], g_Aqh[r * 96 + k], g_Aql[r * 96 + k]);
        red[k] = wv * n1b[k];
        __syncthreads();
        if (k == 0) { float s = 0.f; for (int j = 0; j < 96; j++) s += red[j]; g_bq[r] = s; }
    } else if (r < 800) {
        int c = r - 288;                  // 0..511
        int T = c >> 4, wi = c & 15;
        int g = T * 8 + (wi & 7);
        bool valid = (g < 255);
        const float* W = (wi < 8) ? ffn1_w : ffn2_w;
        float wv = valid ? W[g * 96 + k] : 0.f;
        bsplit(wv * n2w[k], g_Agh[c * 96 + k], g_Agl[c * 96 + k]);
        red[k] = wv * n2b[k];
        __syncthreads();
        if (k == 0) {
            float s = 0.f; for (int j = 0; j < 96; j++) s += red[j];
            if (valid) g_bg[(wi < 8 ? 0 : 256) + g] = s;
        }
    } else if (r < 896) {
        int o = r - 800;                  // 0..95
        for (int kk = k; kk < 256; kk += 96) {
            float v = (kk < 255) ? ffn_out_w[o * 255 + kk] : 0.f;
            bsplit(v, g_Fh[o * 256 + kk], g_Fl[o * 256 + kk]);
        }
    } else {
        for (int j = k; j < BATCH * 204; j += 96) ss[j] = 0.f;
    }
}

// ---------------- LN stats (LN1 only; LN2 fused into gemm epilogue) ----------------
__global__ void ln_stats(const float* __restrict__ x, float* __restrict__ mu,
                         float* __restrict__ rs) {
    int i = blockIdx.x * blockDim.x + threadIdx.x;
    if (i >= BATCH * HW) return;
    int b = i >> 16, pix = i & 65535;
    const float* xp = x + (long long)b * 96 * HW + pix;
    float sum = 0.f, sq = 0.f;
    #pragma unroll 8
    for (int c = 0; c < 96; c++) {
        float v = xp[(long long)c * HW];
        sum += v; sq += v * v;
    }
    float m = sum * (1.f / 96.f);
    float var = sq * (1.f / 96.f) - m * m;
    mu[i] = m;
    rs[i] = rsqrtf(var + 1e-5f);
}

// ---------------- tensor-core GEMM: C[M,65536]=A[M,K]@B, split-bf16 ----------------
// BM in {96,128}, BN=128, BK=32, NT=2*BM threads ((BM/32)x2 warps of 32x64).
// k-major smem, trans ldmatrix (R10-proven core). Grid: x=n-slice (fastest), y=m-tile, z=batch.
// EPI: 0 plain(+RESID), 1 +bias, 2 dual-gate. STATS: fused LN stats (gridDim.y==1, M=96).
template <int BM, int EPI, int LN, int RESID, int STATS>
__global__ __launch_bounds__(2 * BM) void gemm_t(
    const __nv_bfloat16* __restrict__ Ah, const __nv_bfloat16* __restrict__ Al,
    const float* __restrict__ B, const float* __restrict__ R, float* __restrict__ C,
    const float* __restrict__ bias,
    const float* __restrict__ mu, const float* __restrict__ rs,
    float* __restrict__ muo, float* __restrict__ rso,
    int M, int K, int Kpad,
    long long sA, long long sB, long long sR, long long sC)
{
    constexpr int NT = 2 * BM;
    constexpr int NW = NT / 32;                    // warps: 8 or 6
    constexpr int NBJ = (32 + NW - 1) / NW;        // B k-row sweeps: 4 or 6

    extern __shared__ __align__(16) char smem_raw[];
    __nv_bfloat16* Ash = (__nv_bfloat16*)smem_raw;       // [2][32][136]
    __nv_bfloat16* Asl = Ash + 2 * 4352;
    __nv_bfloat16* Bsh = Asl + 2 * 4352;
    __nv_bfloat16* Bsl = Bsh + 2 * 4352;

    Ah += (long long)blockIdx.z * sA;
    Al += (long long)blockIdx.z * sA;
    B  += (long long)blockIdx.z * sB;
    C  += (long long)blockIdx.z * sC;
    if (RESID) R += (long long)blockIdx.z * sR;
    if (LN) { mu += (long long)blockIdx.z * HW; rs += (long long)blockIdx.z * HW; }

    const int m_base = blockIdx.y * BM;
    const int n_base = blockIdx.x * 128;
    const int tid  = threadIdx.x;
    const int lane = tid & 31;
    const int warp = tid >> 5;
    const int wm = warp >> 1, wn = warp & 1;

    // loader coords
    const int bcol = (tid & 31) * 4;   // B col (fixed per thread)
    const int bk0  = warp;             // B k-row base (+NW*j)
    const int am   = tid % BM;         // A m (fixed)
    const int akc0 = tid / BM;         // A k-chunk base (0/1), chunks akc0+2j

    float4 m4, r4;
    if (LN) {
        m4 = *(const float4*)(mu + n_base + bcol);
        r4 = *(const float4*)(rs + n_base + bcol);
    }

    float acc[2][8][4];
    #pragma unroll
    for (int i = 0; i < 2; i++)
        #pragma unroll
        for (int j = 0; j < 8; j++)
            #pragma unroll
            for (int q = 0; q < 4; q++) acc[i][j][q] = 0.f;

    const int nst = (K + 31) >> 5;
    uint4 rgah[2], rgal[2];
    float4 rgb[NBJ];

    // ldmatrix lane-derived offsets
    const int a_row = (lane & 7) + ((lane >> 4) & 1) * 8;
    const int a_col = ((lane >> 3) & 1) * 8;
    const int b_row = (lane & 7) + ((lane >> 3) & 1) * 8;
    const int b_col = ((lane >> 4) & 1) * 8 + wn * 64;

    auto fetch = [&](int kg) {
        #pragma unroll
        for (int j = 0; j < 2; j++) {
            int kc = akc0 + 2 * j;
            int grow = m_base + am;
            if (grow < M) {
                long long off = (long long)grow * Kpad + kg + kc * 8;
                rgah[j] = *(const uint4*)(Ah + off);
                rgal[j] = *(const uint4*)(Al + off);
            } else {
                rgah[j] = make_uint4(0, 0, 0, 0);
                rgal[j] = make_uint4(0, 0, 0, 0);
            }
        }
        #pragma unroll
        for (int j = 0; j < NBJ; j++) {
            int kr = bk0 + NW * j;
            if (kr < 32) {
                int kb = kg + kr;
                if (kb < K) {
                    float4 v = *(const float4*)(B + (long long)kb * HW + n_base + bcol);
                    if (LN) {
                        v.x = (v.x - m4.x) * r4.x; v.y = (v.y - m4.y) * r4.y;
                        v.z = (v.z - m4.z) * r4.z; v.w = (v.w - m4.w) * r4.w;
                    }
                    rgb[j] = v;
                } else {
                    rgb[j] = make_float4(0.f, 0.f, 0.f, 0.f);
                }
            }
        }
    };
    auto stash = [&](int buf) {
        int base = buf * 4352;
        #pragma unroll
        for (int j = 0; j < 2; j++) {
            int kb = (akc0 + 2 * j) * 8;
            const __nv_bfloat16* ph = (const __nv_bfloat16*)&rgah[j];
            const __nv_bfloat16* pl = (const __nv_bfloat16*)&rgal[j];
            #pragma unroll
            for (int rr = 0; rr < 8; rr++) {
                Ash[base + (kb + rr) * 136 + am] = ph[rr];
                Asl[base + (kb + rr) * 136 + am] = pl[rr];
            }
        }
        #pragma unroll
        for (int j = 0; j < NBJ; j++) {
            int kr = bk0 + NW * j;
            if (kr < 32) {
                uint2 h2, l2;
                split2(rgb[j].x, rgb[j].y, h2.x, l2.x);
                split2(rgb[j].z, rgb[j].w, h2.y, l2.y);
                *(uint2*)&Bsh[base + kr * 136 + bcol] = h2;
                *(uint2*)&Bsl[base + kr * 136 + bcol] = l2;
            }
        }
    };

    fetch(0);
    stash(0);
    __syncthreads();

    for (int s = 0; s < nst; s++) {
        int buf = s & 1;
        if (s + 1 < nst) fetch((s + 1) * 32);

        int base = buf * 4352;
        #pragma unroll
        for (int step = 0; step < 2; step++) {
            int k0 = step * 16;
            uint32_t ah[2][4], al[2][4];
            #pragma unroll
            for (int i = 0; i < 2; i++) {
                int col = wm * 32 + i * 16 + a_col;
                int off = base + (k0 + a_row) * 136 + col;
                ldsm4t(ah[i], s2u(&Ash[off]));
                ldsm4t(al[i], s2u(&Asl[off]));
            }
            uint32_t bh[4][4], bl[4][4];
            #pragma unroll
            for (int jp = 0; jp < 4; jp++) {
                int col = b_col + jp * 16;
                int off = base + (k0 + b_row) * 136 + col;
                ldsm4t(bh[jp], s2u(&Bsh[off]));
                ldsm4t(bl[jp], s2u(&Bsl[off]));
            }
            #pragma unroll
            for (int i = 0; i < 2; i++) {
                #pragma unroll
                for (int j = 0; j < 8; j++) {
                    int jp = j >> 1;
                    const uint32_t* bhp = (j & 1) ? bh[jp] + 2 : bh[jp];
                    const uint32_t* blp = (j & 1) ? bl[jp] + 2 : bl[jp];
                    mma_bf16(acc[i][j], ah[i], bhp);
                    mma_bf16(acc[i][j], ah[i], blp);
                    mma_bf16(acc[i][j], al[i], bhp);
                }
            }
        }
        if (s + 1 < nst) stash(buf ^ 1);
        __syncthreads();
    }

    // ---------------- epilogue ----------------
    float ls[16], ls2[16];
    if (STATS) {
        #pragma unroll
        for (int e = 0; e < 16; e++) { ls[e] = 0.f; ls2[e] = 0.f; }
    }

    if (EPI == 2) {
        #pragma unroll
        for (int i = 0; i < 2; i++) {
            int T = (m_base >> 4) + wm * 2 + i;
            int g = T * 8 + (lane >> 2);
            if (g < 255) {
                float b1 = bias[g], b2 = bias[256 + g];
                #pragma unroll
                for (int j = 0; j < 8; j++) {
                    int col = n_base + wn * 64 + j * 8 + 2 * (lane & 3);
                    float2 v;
                    v.x = gatef(acc[i][j][0] + b1, acc[i][j][2] + b2);
                    v.y = gatef(acc[i][j][1] + b1, acc[i][j][3] + b2);
                    *(float2*)(C + (long long)g * HW + col) = v;
                }
            }
        }
    } else {
        #pragma unroll
        for (int i = 0; i < 2; i++) {
            int r0 = m_base + wm * 32 + i * 16 + (lane >> 2);
            int r1 = r0 + 8;
            float bv0 = 0.f, bv1 = 0.f;
            if (EPI == 1) {
                if (r0 < M) bv0 = bias[r0];
                if (r1 < M) bv1 = bias[r1];
            }
            #pragma unroll
            for (int j = 0; j < 8; j++) {
                int col = n_base + wn * 64 + j * 8 + 2 * (lane & 3);
                if (r0 < M) {
                    float2 v = make_float2(acc[i][j][0] + bv0, acc[i][j][1] + bv0);
                    long long o = (long long)r0 * HW + col;
                    if (RESID) { float2 rr = *(const float2*)(R + o); v.x += rr.x; v.y += rr.y; }
                    *(float2*)(C + o) = v;
                    if (STATS) {
                        ls[2 * j] += v.x; ls[2 * j + 1] += v.y;
                        ls2[2 * j] += v.x * v.x; ls2[2 * j + 1] += v.y * v.y;
                    }
                }
                if (r1 < M) {
                    float2 v = make_float2(acc[i][j][2] + bv1, acc[i][j][3] + bv1);
                    long long o = (long long)r1 * HW + col;
                    if (RESID) { float2 rr = *(const float2*)(R + o); v.x += rr.x; v.y += rr.y; }
                    *(float2*)(C + o) = v;
                    if (STATS) {
                        ls[2 * j] += v.x; ls[2 * j + 1] += v.y;
                        ls2[2 * j] += v.x * v.x; ls2[2 * j + 1] += v.y * v.y;
                    }
                }
            }
        }
    }

    if (STATS) {
        __syncthreads();
        float* sstat = (float*)smem_raw;   // [0..127]=sum, [128..255]=sumsq
        for (int t = tid; t < 256; t += NT) sstat[t] = 0.f;
        __syncthreads();
        if (wm < 3) {
            #pragma unroll
            for (int o = 16; o >= 4; o >>= 1) {
                #pragma unroll
                for (int e = 0; e < 16; e++) {
                    ls[e]  += __shfl_down_sync(0xffffffffu, ls[e],  o);
                    ls2[e] += __shfl_down_sync(0xffffffffu, ls2[e], o);
                }
            }
            if (lane < 4) {
                #pragma unroll
                for (int e = 0; e < 16; e++) {
                    int j = e >> 1, q = e & 1;
                    int nl = wn * 64 + j * 8 + 2 * lane + q;
                    atomicAdd(&sstat[nl], ls[e]);
                    atomicAdd(&sstat[128 + nl], ls2[e]);
                }
            }
        }
        __syncthreads();
        if (tid < 128) {
            float sm = sstat[tid] * (1.f / 96.f);
            float sq = sstat[tid + 128] * (1.f / 96.f);
            float var = sq - sm * sm;
            muo[(long long)blockIdx.z * HW + n_base + tid] = sm;
            rso[(long long)blockIdx.z * HW + n_base + tid] = rsqrtf(var + 1e-5f);
        }
    }
}

// ---------------- 3x3 depthwise conv: 32x32 tile, float4 I/O ----------------
__global__ __launch_bounds__(256) void dwconv3(const float* __restrict__ in,
                                               const float* __restrict__ w,
                                               float* __restrict__ out) {
    int zc = blockIdx.z;
    int c = zc % 288;
    const float* src = in  + (long long)zc * HW;
    float*       dst = out + (long long)zc * HW;
    int ox = blockIdx.x * 32, oy = blockIdx.y * 32;
    __shared__ float s[34][40];    // col c <-> gx = ox-4+c ; needed cols 3..36
    int tid = threadIdx.x;
    #pragma unroll
    for (int j = 0; j < 2; j++) {
        int sl = tid + j * 256;
        if (sl < 340) {
            int r = sl / 10, q = sl - r * 10;
            int gy = oy + r - 1, gx = ox - 4 + q * 4;
            float4 v = make_float4(0.f, 0.f, 0.f, 0.f);
            if (gy >= 0 && gy < 256 && gx >= 0 && gx <= 252)
                v = *(const float4*)(src + gy * 256 + gx);
            *(float4*)&s[r][q * 4] = v;
        }
    }
    __syncthreads();
    const float* wc = w + c * 9;
    float w00 = wc[0], w01 = wc[1], w02 = wc[2];
    float w10 = wc[3], w11 = wc[4], w12 = wc[5];
    float w20 = wc[6], w21 = wc[7], w22 = wc[8];
    int row  = tid >> 3;           // 0..31
    int colq = (tid & 7) * 4;      // 0..28
    float v[3][6];
    #pragma unroll
    for (int dr = 0; dr < 3; dr++) {
        float4 m = *(const float4*)&s[row + dr][colq + 4];
        v[dr][0] = s[row + dr][colq + 3];
        v[dr][1] = m.x; v[dr][2] = m.y; v[dr][3] = m.z; v[dr][4] = m.w;
        v[dr][5] = s[row + dr][colq + 8];
    }
    float4 o;
    float* op = (float*)&o;
    #pragma unroll
    for (int t = 0; t < 4; t++) {
        op[t] = w00 * v[0][t] + w01 * v[0][t + 1] + w02 * v[0][t + 2]
              + w10 * v[1][t] + w11 * v[1][t + 1] + w12 * v[1][t + 2]
              + w20 * v[2][t] + w21 * v[2][t + 1] + w22 * v[2][t + 2];
    }
    *(float4*)(dst + (oy + row) * 256 + ox + colq) = o;
}

// ---------------- svp 1x1 conv ----------------
__global__ void svp_kernel(const float* __restrict__ fea, const float* __restrict__ w,
                           float* __restrict__ out) {
    int i = blockIdx.x * blockDim.x + threadIdx.x;
    if (i >= BATCH * HW) return;
    int b = i >> 16, pix = i & 65535;
    const float* f = fea + (long long)b * 3 * HW + pix;
    float f0 = f[0], f1 = f[HW], f2 = f[2 * HW];
    float* o = out + (long long)b * 12 * HW + pix;
    #pragma unroll
    for (int r = 0; r < 12; r++)
        o[(long long)r * HW] = w[r * 3] * f0 + w[r * 3 + 1] * f1 + w[r * 3 + 2] * f2;
}

// ---------------- Gram partials + fused per-row sum of squares ----------------
__global__ __launch_bounds__(672) void gram_kernel(const float* __restrict__ qkvd,
                                                   const float* __restrict__ svpq,
                                                   float* __restrict__ gp,
                                                   float* __restrict__ ss) {
    __shared__ float qs[27 * GPAD];
    __shared__ float ks[24 * GPAD];
    __shared__ float red_s[51];
    int seg = blockIdx.x;
    int bh  = blockIdx.y;
    int b = bh >> 2, h = bh & 3;
    int tid = threadIdx.x;
    int c = tid / 24, d = tid % 24;
    bool active = tid < 648;
    long long segoff = (long long)seg * (HW / NSEG);
    float acc = 0.f;
    float sqacc[3] = {0.f, 0.f, 0.f};
    if (tid < 51) red_s[tid] = 0.f;

    for (int ch = 0; ch < HW / NSEG; ch += GCH) {
        int jj = 0;
        for (int i = tid; i < 51 * (GCH / 4); i += 672, jj++) {
            int row = i / (GCH / 4), col4 = i % (GCH / 4);
            const float* src;
            float* dstb;
            if (row < 27) {
                src = (row < 24) ? qkvd + ((long long)b * 288 + h * 24 + row) * HW
                                 : svpq + ((long long)b * 12 + h * 3 + (row - 24)) * HW;
                dstb = qs + row * GPAD;
            } else {
                int rr = row - 27;
                src = qkvd + ((long long)b * 288 + 96 + h * 24 + rr) * HW;
                dstb = ks + rr * GPAD;
            }
            float4 v = *(const float4*)(src + segoff + ch + col4 * 4);
            *(float4*)(dstb + col4 * 4) = v;
            sqacc[jj] += v.x * v.x + v.y * v.y + v.z * v.z + v.w * v.w;
        }
        __syncthreads();
        if (active) {
            const float4* q4 = (const float4*)(qs + c * GPAD);
            const float4* k4 = (const float4*)(ks + d * GPAD);
            #pragma unroll 8
            for (int p = 0; p < GCH / 4; p++) {
                float4 qv = q4[p], kv = k4[p];
                acc += qv.x * kv.x + qv.y * kv.y + qv.z * kv.z + qv.w * kv.w;
            }
        }
        __syncthreads();
    }
    if (active) gp[((long long)seg * 16 + bh) * 648 + tid] = acc;

    // flush fused sumsq
    {
        int jj = 0;
        for (int i = tid; i < 51 * (GCH / 4); i += 672, jj++) {
            int row = i / (GCH / 4);
            atomicAdd(&red_s[row], sqacc[jj]);
        }
    }
    __syncthreads();
    if (tid < 51) {
        int row = tid;
        int idx;
        if (row < 24)       idx = b * 204 + h * 24 + row;
        else if (row < 27)  idx = b * 204 + 192 + h * 3 + (row - 24);
        else                idx = b * 204 + 96 + h * 24 + (row - 27);
        atomicAdd(&ss[idx], red_s[row]);
    }
}

// ---------------- attn softmax + fold proj_out -> M[b] (bf16 split) ----------------
__global__ void attnm_kernel(const float* __restrict__ gp, const float* __restrict__ ss,
                             const float* __restrict__ temp, const float* __restrict__ projw,
                             __nv_bfloat16* __restrict__ Mh, __nv_bfloat16* __restrict__ Ml) {
    int b = blockIdx.x;
    __shared__ float attn_s[4][27][24];
    int tid = threadIdx.x;
    if (tid < 108) {
        int h = tid / 27, c = tid % 27;
        float ssq = (c < 24) ? ss[b * 204 + h * 24 + c]
                             : ss[b * 204 + 192 + h * 3 + (c - 24)];
        float nq = fmaxf(sqrtf(ssq), 1e-12f);
        float t = temp[h];
        float row[24];
        #pragma unroll
        for (int d = 0; d < 24; d++) {
            float g = 0.f;
            for (int s = 0; s < NSEG; s++)
                g += gp[((long long)s * 16 + b * 4 + h) * 648 + c * 24 + d];
            float nk = fmaxf(sqrtf(ss[b * 204 + 96 + h * 24 + d]), 1e-12f);
            row[d] = g * t / (nq * nk);
        }
        float mx = row[0];
        #pragma unroll
        for (int d = 1; d < 24; d++) mx = fmaxf(mx, row[d]);
        float sum = 0.f;
        #pragma unroll
        for (int d = 0; d < 24; d++) { row[d] = expf(row[d] - mx); sum += row[d]; }
        float inv = 1.f / sum;
        #pragma unroll
        for (int d = 0; d < 24; d++) attn_s[h][c][d] = row[d] * inv;
    }
    __syncthreads();
    for (int e = tid; e < 96 * 96; e += blockDim.x) {
        int o = e / 96, col = e % 96;
        int h = col / 24, d = col % 24;
        float s = 0.f;
        #pragma unroll
        for (int c = 0; c < 27; c++)
            s += projw[o * 108 + h * 27 + c] * attn_s[h][c][d];
        bsplit(s, Mh[b * 9216 + e], Ml[b * 9216 + e]);
    }
}

// ---------------- launch ----------------
extern "C" void kernel_launch(void* const* d_in, const int* in_sizes, int n_in,
                              void* d_out, int out_size) {
    const float* x           = (const float*)d_in[0];
    const float* svp_fea     = (const float*)d_in[1];
    const float* n1w         = (const float*)d_in[2];
    const float* n1b         = (const float*)d_in[3];
    const float* qkv_w       = (const float*)d_in[4];
    const float* qkv_dw_w    = (const float*)d_in[5];
    const float* svp_w       = (const float*)d_in[6];
    const float* temperature = (const float*)d_in[7];
    const float* proj_out_w  = (const float*)d_in[8];
    const float* n2w         = (const float*)d_in[9];
    const float* n2b         = (const float*)d_in[10];
    const float* ffn1_w      = (const float*)d_in[11];
    const float* ffn2_w      = (const float*)d_in[12];
    const float* ffn_out_w   = (const float*)d_in[13];
    float* out = (float*)d_out;

    float *qkv, *qkvd, *svpq, *mu, *rs, *ss, *gp, *bq, *bg;
    __nv_bfloat16 *Mh, *Ml, *Aqh, *Aql, *Agh, *Agl, *Fh, *Fl;
    cudaGetSymbolAddress((void**)&qkv,  g_qkv);
    cudaGetSymbolAddress((void**)&qkvd, g_qkvd);
    cudaGetSymbolAddress((void**)&svpq, g_svpq);
    cudaGetSymbolAddress((void**)&mu,   g_mu);
    cudaGetSymbolAddress((void**)&rs,   g_rs);
    cudaGetSymbolAddress((void**)&ss,   g_ss);
    cudaGetSymbolAddress((void**)&gp,   g_gp);
    cudaGetSymbolAddress((void**)&Mh,   g_Mh);
    cudaGetSymbolAddress((void**)&Ml,   g_Ml);
    cudaGetSymbolAddress((void**)&Aqh,  g_Aqh);
    cudaGetSymbolAddress((void**)&Aql,  g_Aql);
    cudaGetSymbolAddress((void**)&bq,   g_bq);
    cudaGetSymbolAddress((void**)&Agh,  g_Agh);
    cudaGetSymbolAddress((void**)&Agl,  g_Agl);
    cudaGetSymbolAddress((void**)&bg,   g_bg);
    cudaGetSymbolAddress((void**)&Fh,   g_Fh);
    cudaGetSymbolAddress((void**)&Fl,   g_Fl);

    const int GEMM_SMEM = 4 * 2 * 32 * 136 * 2;   // 69632 bytes
    cudaFuncSetAttribute(gemm_t<96, 1, 1, 0, 0>, cudaFuncAttributeMaxDynamicSharedMemorySize, GEMM_SMEM);
    cudaFuncSetAttribute(gemm_t<96, 0, 0, 1, 1>, cudaFuncAttributeMaxDynamicSharedMemorySize, GEMM_SMEM);
    cudaFuncSetAttribute(gemm_t<128, 2, 1, 0, 0>, cudaFuncAttributeMaxDynamicSharedMemorySize, GEMM_SMEM);
    cudaFuncSetAttribute(gemm_t<96, 0, 0, 1, 0>, cudaFuncAttributeMaxDynamicSharedMemorySize, GEMM_SMEM);

    const int pixBlocks = (BATCH * HW + 255) / 256;

    // 0. fold LN weights into split-bf16 A matrices; zero ss
    prep_kernel<<<897, 96>>>(qkv_w, n1w, n1b, ffn1_w, ffn2_w, n2w, n2b, ffn_out_w, ss);
    // 1. LN1 stats
    ln_stats<<<pixBlocks, 256>>>(x, mu, rs);
    // 2. qkv = Aq @ LN(x) + bq   [3 exact 96-row tiles]
    gemm_t<96, 1, 1, 0, 0><<<dim3(512, 3, BATCH), 192, GEMM_SMEM>>>(Aqh, Aql, x, nullptr, qkv,
        bq, mu, rs, nullptr, nullptr, 288, 96, 96, 0, 96LL * HW, 0, 288LL * HW);
    // 3. depthwise 3x3
    dwconv3<<<dim3(8, 8, BATCH * 288), 256>>>(qkv, qkv_dw_w, qkvd);
    // 4. svp_q
    svp_kernel<<<pixBlocks, 256>>>(svp_fea, svp_w, svpq);
    // 5. Gram partials + fused sumsq
    gram_kernel<<<dim3(NSEG, 16), 672>>>(qkvd, svpq, gp, ss);
    // 6. softmax + fold proj_out -> M[b]
    attnm_kernel<<<BATCH, 128>>>(gp, ss, temperature, proj_out_w, Mh, Ml);
    // 7. x2 = x + M_b @ v -> out, fused LN2 stats  [exact 96 rows]
    gemm_t<96, 0, 0, 1, 1><<<dim3(512, 1, BATCH), 192, GEMM_SMEM>>>(Mh, Ml, qkvd + 192LL * HW, x, out,
        nullptr, nullptr, nullptr, mu, rs, 96, 96, 96, 9216, 288LL * HW, 96LL * HW, 96LL * HW);
    // 8. interleaved ffn1/ffn2 GEMM + fused dual-gate -> g (qkv buffer)  [M=512 exact at BM=128]
    gemm_t<128, 2, 1, 0, 0><<<dim3(512, 4, BATCH), 256, GEMM_SMEM>>>(Agh, Agl, out, nullptr, qkv,
        bg, mu, rs, nullptr, nullptr, 512, 96, 96, 0, 96LL * HW, 0, 288LL * HW);
    // 9. out = out + ffn_out_w @ g  [exact 96 rows, K=255]
    gemm_t<96, 0, 0, 1, 0><<<dim3(512, 1, BATCH), 192, GEMM_SMEM>>>(Fh, Fl, qkv, out, out,
        nullptr, nullptr, nullptr, nullptr, nullptr, 96, 255, 256, 0, 288LL * HW, 96LL * HW, 96LL * HW);
}

// round 14
// speedup vs baseline: 1.1987x; 1.0502x over previous
#include <cuda_runtime.h>
#include <cuda_bf16.h>
#include <math.h>
#include <stdint.h>

#define HW 65536
#define BATCH 4
#define NSEG 32
#define GCH 128
#define GPAD 140

// ---------------- static scratch ----------------
__device__ __nv_bfloat16 g_qkv [(size_t)BATCH * 288 * HW]; // qkv pre-dwconv (bf16); later gated FFN 'g' (bf16)
__device__ float g_qkvd[(size_t)BATCH * 288 * HW];          // qkv post-dwconv (q|k|v) fp32
__device__ float g_svpq[(size_t)BATCH * 12  * HW];          // svp_q
__device__ float g_mu  [(size_t)BATCH * HW];
__device__ float g_rs  [(size_t)BATCH * HW];
__device__ float g_ss  [BATCH * 204];
__device__ float g_gp  [NSEG * 16 * 648];
__device__ __nv_bfloat16 g_Mh [BATCH * 96 * 96];
__device__ __nv_bfloat16 g_Ml [BATCH * 96 * 96];
__device__ __nv_bfloat16 g_Aqh[288 * 96];
__device__ __nv_bfloat16 g_Aql[288 * 96];
__device__ float g_bq  [288];
__device__ __nv_bfloat16 g_Agh[512 * 96];
__device__ __nv_bfloat16 g_Agl[512 * 96];
__device__ float g_bg  [512];
__device__ __nv_bfloat16 g_Fh [96 * 256];
__device__ __nv_bfloat16 g_Fl [96 * 256];

// ---------------- helpers ----------------
__device__ __forceinline__ void bsplit(float v, __nv_bfloat16& h, __nv_bfloat16& l) {
    h = __float2bfloat16(v);
    l = __float2bfloat16(v - __bfloat162float(h));
}
__device__ __forceinline__ void split2(float a, float b, uint32_t& h, uint32_t& l) {
    __nv_bfloat16 ha = __float2bfloat16(a), hb = __float2bfloat16(b);
    __nv_bfloat16 la = __float2bfloat16(a - __bfloat162float(ha));
    __nv_bfloat16 lb = __float2bfloat16(b - __bfloat162float(hb));
    __nv_bfloat162 hv(ha, hb), lv(la, lb);
    h = *(uint32_t*)&hv; l = *(uint32_t*)&lv;
}
__device__ __forceinline__ uint32_t s2u(const void* p) {
    return (uint32_t)__cvta_generic_to_shared(p);
}
__device__ __forceinline__ void ldsm4t(uint32_t* r, uint32_t addr) {
    asm volatile("ldmatrix.sync.aligned.m8n8.x4.trans.shared.b16 {%0,%1,%2,%3}, [%4];"
        : "=r"(r[0]), "=r"(r[1]), "=r"(r[2]), "=r"(r[3]) : "r"(addr));
}
__device__ __forceinline__ void mma_bf16(float* d, const uint32_t* a, const uint32_t* b) {
    asm volatile("mma.sync.aligned.m16n8k16.row.col.f32.bf16.bf16.f32 "
        "{%0,%1,%2,%3}, {%4,%5,%6,%7}, {%8,%9}, {%0,%1,%2,%3};"
        : "+f"(d[0]), "+f"(d[1]), "+f"(d[2]), "+f"(d[3])
        : "r"(a[0]), "r"(a[1]), "r"(a[2]), "r"(a[3]), "r"(b[0]), "r"(b[1]));
}
__device__ __forceinline__ float gatef(float a, float bb) {
    float sig = 1.f / (1.f + expf(-bb));
    float gel = 0.5f * a * (1.f + erff(a * 0.70710678118654752f));
    return a * sig + bb * gel;
}

// ---------------- prep: fold LN weights, split to bf16 hi/lo, zero ss ----------------
__global__ void prep_kernel(const float* __restrict__ qkv_w,
                            const float* __restrict__ n1w, const float* __restrict__ n1b,
                            const float* __restrict__ ffn1_w, const float* __restrict__ ffn2_w,
                            const float* __restrict__ n2w, const float* __restrict__ n2b,
                            const float* __restrict__ ffn_out_w, float* __restrict__ ss) {
    int r = blockIdx.x;
    int k = threadIdx.x;  // 0..95
    __shared__ float red[96];
    if (r < 288) {
        float wv = qkv_w[r * 96 + k];
        bsplit(wv * n1w[k], g_Aqh[r * 96 + k], g_Aql[r * 96 + k]);
        red[k] = wv * n1b[k];
        __syncthreads();
        if (k == 0) { float s = 0.f; for (int j = 0; j < 96; j++) s += red[j]; g_bq[r] = s; }
    } else if (r < 800) {
        int c = r - 288;                  // 0..511
        int T = c >> 4, wi = c & 15;
        int g = T * 8 + (wi & 7);
        bool valid = (g < 255);
        const float* W = (wi < 8) ? ffn1_w : ffn2_w;
        float wv = valid ? W[g * 96 + k] : 0.f;
        bsplit(wv * n2w[k], g_Agh[c * 96 + k], g_Agl[c * 96 + k]);
        red[k] = wv * n2b[k];
        __syncthreads();
        if (k == 0) {
            float s = 0.f; for (int j = 0; j < 96; j++) s += red[j];
            if (valid) g_bg[(wi < 8 ? 0 : 256) + g] = s;
        }
    } else if (r < 896) {
        int o = r - 800;                  // 0..95
        for (int kk = k; kk < 256; kk += 96) {
            float v = (kk < 255) ? ffn_out_w[o * 255 + kk] : 0.f;
            bsplit(v, g_Fh[o * 256 + kk], g_Fl[o * 256 + kk]);
        }
    } else {
        for (int j = k; j < BATCH * 204; j += 96) ss[j] = 0.f;
    }
}

// ---------------- LN stats (LN1 only; LN2 fused into gemm epilogue) ----------------
__global__ void ln_stats(const float* __restrict__ x, float* __restrict__ mu,
                         float* __restrict__ rs) {
    int i = blockIdx.x * blockDim.x + threadIdx.x;
    if (i >= BATCH * HW) return;
    int b = i >> 16, pix = i & 65535;
    const float* xp = x + (long long)b * 96 * HW + pix;
    float sum = 0.f, sq = 0.f;
    #pragma unroll 8
    for (int c = 0; c < 96; c++) {
        float v = xp[(long long)c * HW];
        sum += v; sq += v * v;
    }
    float m = sum * (1.f / 96.f);
    float var = sq * (1.f / 96.f) - m * m;
    mu[i] = m;
    rs[i] = rsqrtf(var + 1e-5f);
}

// ---------------- tensor-core GEMM: C[M,65536]=A[M,K]@B, split-bf16 ----------------
// BM in {96,128}, BN=128, BK=32, NT=2*BM threads. k-major smem, trans ldmatrix.
// EPI: 0 plain(+RESID), 1 +bias, 2 dual-gate. STATS: fused LN stats (gridDim.y==1, M=96).
// OBF16: C is bf16.  BEXACT: B is bf16 (exact) -> 2-term MMA, no Bsl.
template <int BM, int EPI, int LN, int RESID, int STATS, int OBF16, int BEXACT>
__global__ __launch_bounds__(2 * BM) void gemm_t(
    const __nv_bfloat16* __restrict__ Ah, const __nv_bfloat16* __restrict__ Al,
    const void* __restrict__ Bv, const float* __restrict__ R, void* __restrict__ Cv,
    const float* __restrict__ bias,
    const float* __restrict__ mu, const float* __restrict__ rs,
    float* __restrict__ muo, float* __restrict__ rso,
    int M, int K, int Kpad,
    long long sA, long long sB, long long sR, long long sC)
{
    constexpr int NT = 2 * BM;
    constexpr int NW = NT / 32;                    // warps: 8 or 6
    constexpr int NBJ = (32 + NW - 1) / NW;        // B k-row sweeps

    extern __shared__ __align__(16) char smem_raw[];
    __nv_bfloat16* Ash = (__nv_bfloat16*)smem_raw;       // [2][32][136]
    __nv_bfloat16* Asl = Ash + 2 * 4352;
    __nv_bfloat16* Bsh = Asl + 2 * 4352;
    __nv_bfloat16* Bsl = Bsh + 2 * 4352;

    Ah += (long long)blockIdx.z * sA;
    Al += (long long)blockIdx.z * sA;
    const float*         Bf = (const float*)Bv         + (long long)blockIdx.z * sB;
    const __nv_bfloat16* Bb = (const __nv_bfloat16*)Bv + (long long)blockIdx.z * sB;
    float*         Cf = (float*)Cv         + (long long)blockIdx.z * sC;
    __nv_bfloat16* Cb = (__nv_bfloat16*)Cv + (long long)blockIdx.z * sC;
    if (RESID) R += (long long)blockIdx.z * sR;
    if (LN) { mu += (long long)blockIdx.z * HW; rs += (long long)blockIdx.z * HW; }

    const int m_base = blockIdx.y * BM;
    const int n_base = blockIdx.x * 128;
    const int tid  = threadIdx.x;
    const int lane = tid & 31;
    const int warp = tid >> 5;
    const int wm = warp >> 1, wn = warp & 1;

    // loader coords
    const int bcol = (tid & 31) * 4;   // B col (fixed per thread)
    const int bk0  = warp;             // B k-row base (+NW*j)
    const int am   = tid % BM;         // A m (fixed)
    const int akc0 = tid / BM;         // A k-chunk base (0/1), chunks akc0+2j

    float4 m4, r4;
    if (LN) {
        m4 = *(const float4*)(mu + n_base + bcol);
        r4 = *(const float4*)(rs + n_base + bcol);
    }

    float acc[2][8][4];
    #pragma unroll
    for (int i = 0; i < 2; i++)
        #pragma unroll
        for (int j = 0; j < 8; j++)
            #pragma unroll
            for (int q = 0; q < 4; q++) acc[i][j][q] = 0.f;

    const int nst = (K + 31) >> 5;
    uint4 rgah[2], rgal[2];
    float4 rgb[NBJ];
    uint2 rbex[NBJ];

    // ldmatrix lane-derived offsets
    const int a_row = (lane & 7) + ((lane >> 4) & 1) * 8;
    const int a_col = ((lane >> 3) & 1) * 8;
    const int b_row = (lane & 7) + ((lane >> 3) & 1) * 8;
    const int b_col = ((lane >> 4) & 1) * 8 + wn * 64;

    auto fetch = [&](int kg) {
        #pragma unroll
        for (int j = 0; j < 2; j++) {
            int kc = akc0 + 2 * j;
            int grow = m_base + am;
            if (grow < M) {
                long long off = (long long)grow * Kpad + kg + kc * 8;
                rgah[j] = *(const uint4*)(Ah + off);
                rgal[j] = *(const uint4*)(Al + off);
            } else {
                rgah[j] = make_uint4(0, 0, 0, 0);
                rgal[j] = make_uint4(0, 0, 0, 0);
            }
        }
        #pragma unroll
        for (int j = 0; j < NBJ; j++) {
            int kr = bk0 + NW * j;
            if (kr < 32) {
                int kb = kg + kr;
                if (BEXACT) {
                    rbex[j] = (kb < K) ? *(const uint2*)(Bb + (long long)kb * HW + n_base + bcol)
                                       : make_uint2(0, 0);
                } else {
                    if (kb < K) {
                        float4 v = *(const float4*)(Bf + (long long)kb * HW + n_base + bcol);
                        if (LN) {
                            v.x = (v.x - m4.x) * r4.x; v.y = (v.y - m4.y) * r4.y;
                            v.z = (v.z - m4.z) * r4.z; v.w = (v.w - m4.w) * r4.w;
                        }
                        rgb[j] = v;
                    } else {
                        rgb[j] = make_float4(0.f, 0.f, 0.f, 0.f);
                    }
                }
            }
        }
    };
    auto stash = [&](int buf) {
        int base = buf * 4352;
        #pragma unroll
        for (int j = 0; j < 2; j++) {
            int kb = (akc0 + 2 * j) * 8;
            const __nv_bfloat16* ph = (const __nv_bfloat16*)&rgah[j];
            const __nv_bfloat16* pl = (const __nv_bfloat16*)&rgal[j];
            #pragma unroll
            for (int rr = 0; rr < 8; rr++) {
                Ash[base + (kb + rr) * 136 + am] = ph[rr];
                Asl[base + (kb + rr) * 136 + am] = pl[rr];
            }
        }
        #pragma unroll
        for (int j = 0; j < NBJ; j++) {
            int kr = bk0 + NW * j;
            if (kr < 32) {
                if (BEXACT) {
                    *(uint2*)&Bsh[base + kr * 136 + bcol] = rbex[j];
                } else {
                    uint2 h2, l2;
                    split2(rgb[j].x, rgb[j].y, h2.x, l2.x);
                    split2(rgb[j].z, rgb[j].w, h2.y, l2.y);
                    *(uint2*)&Bsh[base + kr * 136 + bcol] = h2;
                    *(uint2*)&Bsl[base + kr * 136 + bcol] = l2;
                }
            }
        }
    };

    fetch(0);
    stash(0);
    __syncthreads();

    for (int s = 0; s < nst; s++) {
        int buf = s & 1;
        if (s + 1 < nst) fetch((s + 1) * 32);

        int base = buf * 4352;
        #pragma unroll
        for (int step = 0; step < 2; step++) {
            int k0 = step * 16;
            uint32_t ah[2][4], al[2][4];
            #pragma unroll
            for (int i = 0; i < 2; i++) {
                int col = wm * 32 + i * 16 + a_col;
                int off = base + (k0 + a_row) * 136 + col;
                ldsm4t(ah[i], s2u(&Ash[off]));
                ldsm4t(al[i], s2u(&Asl[off]));
            }
            uint32_t bh[4][4], bl[4][4];
            #pragma unroll
            for (int jp = 0; jp < 4; jp++) {
                int col = b_col + jp * 16;
                int off = base + (k0 + b_row) * 136 + col;
                ldsm4t(bh[jp], s2u(&Bsh[off]));
                if (!BEXACT) ldsm4t(bl[jp], s2u(&Bsl[off]));
            }
            #pragma unroll
            for (int i = 0; i < 2; i++) {
                #pragma unroll
                for (int j = 0; j < 8; j++) {
                    int jp = j >> 1;
                    const uint32_t* bhp = (j & 1) ? bh[jp] + 2 : bh[jp];
                    mma_bf16(acc[i][j], ah[i], bhp);
                    if (!BEXACT) {
                        const uint32_t* blp = (j & 1) ? bl[jp] + 2 : bl[jp];
                        mma_bf16(acc[i][j], ah[i], blp);
                    }
                    mma_bf16(acc[i][j], al[i], bhp);
                }
            }
        }
        if (s + 1 < nst) stash(buf ^ 1);
        __syncthreads();
    }

    // ---------------- epilogue ----------------
    float ls[16], ls2[16];
    if (STATS) {
        #pragma unroll
        for (int e = 0; e < 16; e++) { ls[e] = 0.f; ls2[e] = 0.f; }
    }

    if (EPI == 2) {
        #pragma unroll
        for (int i = 0; i < 2; i++) {
            int T = (m_base >> 4) + wm * 2 + i;
            int g = T * 8 + (lane >> 2);
            if (g < 255) {
                float b1 = bias[g], b2 = bias[256 + g];
                #pragma unroll
                for (int j = 0; j < 8; j++) {
                    int col = n_base + wn * 64 + j * 8 + 2 * (lane & 3);
                    float vx = gatef(acc[i][j][0] + b1, acc[i][j][2] + b2);
                    float vy = gatef(acc[i][j][1] + b1, acc[i][j][3] + b2);
                    if (OBF16) {
                        __nv_bfloat162 bv2(__float2bfloat16(vx), __float2bfloat16(vy));
                        *(__nv_bfloat162*)(Cb + (long long)g * HW + col) = bv2;
                    } else {
                        *(float2*)(Cf + (long long)g * HW + col) = make_float2(vx, vy);
                    }
                }
            }
        }
    } else {
        #pragma unroll
        for (int i = 0; i < 2; i++) {
            int r0 = m_base + wm * 32 + i * 16 + (lane >> 2);
            int r1 = r0 + 8;
            float bv0 = 0.f, bv1 = 0.f;
            if (EPI == 1) {
                if (r0 < M) bv0 = bias[r0];
                if (r1 < M) bv1 = bias[r1];
            }
            #pragma unroll
            for (int j = 0; j < 8; j++) {
                int col = n_base + wn * 64 + j * 8 + 2 * (lane & 3);
                #pragma unroll
                for (int half = 0; half < 2; half++) {
                    int rr = half ? r1 : r0;
                    if (rr >= M) continue;
                    float bv = half ? bv1 : bv0;
                    float vx = acc[i][j][half * 2 + 0] + bv;
                    float vy = acc[i][j][half * 2 + 1] + bv;
                    long long o = (long long)rr * HW + col;
                    if (RESID) {
                        float2 rv = *(const float2*)(R + o);
                        vx += rv.x; vy += rv.y;
                    }
                    if (OBF16) {
                        __nv_bfloat162 bv2(__float2bfloat16(vx), __float2bfloat16(vy));
                        *(__nv_bfloat162*)(Cb + o) = bv2;
                    } else {
                        *(float2*)(Cf + o) = make_float2(vx, vy);
                    }
                    if (STATS) {
                        ls[2 * j] += vx; ls[2 * j + 1] += vy;
                        ls2[2 * j] += vx * vx; ls2[2 * j + 1] += vy * vy;
                    }
                }
            }
        }
    }

    if (STATS) {
        __syncthreads();
        float* sstat = (float*)smem_raw;   // [0..127]=sum, [128..255]=sumsq
        for (int t = tid; t < 256; t += NT) sstat[t] = 0.f;
        __syncthreads();
        if (wm < 3) {
            #pragma unroll
            for (int o = 16; o >= 4; o >>= 1) {
                #pragma unroll
                for (int e = 0; e < 16; e++) {
                    ls[e]  += __shfl_down_sync(0xffffffffu, ls[e],  o);
                    ls2[e] += __shfl_down_sync(0xffffffffu, ls2[e], o);
                }
            }
            if (lane < 4) {
                #pragma unroll
                for (int e = 0; e < 16; e++) {
                    int j = e >> 1, q = e & 1;
                    int nl = wn * 64 + j * 8 + 2 * lane + q;
                    atomicAdd(&sstat[nl], ls[e]);
                    atomicAdd(&sstat[128 + nl], ls2[e]);
                }
            }
        }
        __syncthreads();
        if (tid < 128) {
            float sm = sstat[tid] * (1.f / 96.f);
            float sq = sstat[tid + 128] * (1.f / 96.f);
            float var = sq - sm * sm;
            muo[(long long)blockIdx.z * HW + n_base + tid] = sm;
            rso[(long long)blockIdx.z * HW + n_base + tid] = rsqrtf(var + 1e-5f);
        }
    }
}

// ---------------- 3x3 depthwise conv: 32x32 tile, bf16 in / fp32 out ----------------
__global__ __launch_bounds__(256) void dwconv3(const __nv_bfloat16* __restrict__ in,
                                               const float* __restrict__ w,
                                               float* __restrict__ out) {
    int zc = blockIdx.z;
    int c = zc % 288;
    const __nv_bfloat16* src = in + (long long)zc * HW;
    float* dst = out + (long long)zc * HW;
    int ox = blockIdx.x * 32, oy = blockIdx.y * 32;
    __shared__ float s[34][40];    // col q*4 <-> gx = ox-4+q*4 ; needed cols 3..36
    int tid = threadIdx.x;
    #pragma unroll
    for (int j = 0; j < 2; j++) {
        int sl = tid + j * 256;
        if (sl < 340) {
            int r = sl / 10, q = sl - r * 10;
            int gy = oy + r - 1, gx = ox - 4 + q * 4;
            float4 v = make_float4(0.f, 0.f, 0.f, 0.f);
            if (gy >= 0 && gy < 256 && gx >= 0 && gx <= 252) {
                uint2 u = *(const uint2*)(src + gy * 256 + gx);
                __nv_bfloat162 p0 = *(__nv_bfloat162*)&u.x;
                __nv_bfloat162 p1 = *(__nv_bfloat162*)&u.y;
                v.x = __low2float(p0); v.y = __high2float(p0);
                v.z = __low2float(p1); v.w = __high2float(p1);
            }
            *(float4*)&s[r][q * 4] = v;
        }
    }
    __syncthreads();
    const float* wc = w + c * 9;
    float w00 = wc[0], w01 = wc[1], w02 = wc[2];
    float w10 = wc[3], w11 = wc[4], w12 = wc[5];
    float w20 = wc[6], w21 = wc[7], w22 = wc[8];
    int row  = tid >> 3;           // 0..31
    int colq = (tid & 7) * 4;      // 0..28
    float v[3][6];
    #pragma unroll
    for (int dr = 0; dr < 3; dr++) {
        float4 m = *(const float4*)&s[row + dr][colq + 4];
        v[dr][0] = s[row + dr][colq + 3];
        v[dr][1] = m.x; v[dr][2] = m.y; v[dr][3] = m.z; v[dr][4] = m.w;
        v[dr][5] = s[row + dr][colq + 8];
    }
    float4 o;
    float* op = (float*)&o;
    #pragma unroll
    for (int t = 0; t < 4; t++) {
        op[t] = w00 * v[0][t] + w01 * v[0][t + 1] + w02 * v[0][t + 2]
              + w10 * v[1][t] + w11 * v[1][t + 1] + w12 * v[1][t + 2]
              + w20 * v[2][t] + w21 * v[2][t + 1] + w22 * v[2][t + 2];
    }
    *(float4*)(dst + (oy + row) * 256 + ox + colq) = o;
}

// ---------------- svp 1x1 conv ----------------
__global__ void svp_kernel(const float* __restrict__ fea, const float* __restrict__ w,
                           float* __restrict__ out) {
    int i = blockIdx.x * blockDim.x + threadIdx.x;
    if (i >= BATCH * HW) return;
    int b = i >> 16, pix = i & 65535;
    const float* f = fea + (long long)b * 3 * HW + pix;
    float f0 = f[0], f1 = f[HW], f2 = f[2 * HW];
    float* o = out + (long long)b * 12 * HW + pix;
    #pragma unroll
    for (int r = 0; r < 12; r++)
        o[(long long)r * HW] = w[r * 3] * f0 + w[r * 3 + 1] * f1 + w[r * 3 + 2] * f2;
}

// ---------------- Gram partials + fused per-row sum of squares ----------------
__global__ __launch_bounds__(672) void gram_kernel(const float* __restrict__ qkvd,
                                                   const float* __restrict__ svpq,
                                                   float* __restrict__ gp,
                                                   float* __restrict__ ss) {
    __shared__ float qs[27 * GPAD];
    __shared__ float ks[24 * GPAD];
    __shared__ float red_s[51];
    int seg = blockIdx.x;
    int bh  = blockIdx.y;
    int b = bh >> 2, h = bh & 3;
    int tid = threadIdx.x;
    int c = tid / 24, d = tid % 24;
    bool active = tid < 648;
    long long segoff = (long long)seg * (HW / NSEG);
    float acc = 0.f;
    float sqacc[3] = {0.f, 0.f, 0.f};
    if (tid < 51) red_s[tid] = 0.f;

    for (int ch = 0; ch < HW / NSEG; ch += GCH) {
        int jj = 0;
        for (int i = tid; i < 51 * (GCH / 4); i += 672, jj++) {
            int row = i / (GCH / 4), col4 = i % (GCH / 4);
            const float* src;
            float* dstb;
            if (row < 27) {
                src = (row < 24) ? qkvd + ((long long)b * 288 + h * 24 + row) * HW
                                 : svpq + ((long long)b * 12 + h * 3 + (row - 24)) * HW;
                dstb = qs + row * GPAD;
            } else {
                int rr = row - 27;
                src = qkvd + ((long long)b * 288 + 96 + h * 24 + rr) * HW;
                dstb = ks + rr * GPAD;
            }
            float4 v = *(const float4*)(src + segoff + ch + col4 * 4);
            *(float4*)(dstb + col4 * 4) = v;
            sqacc[jj] += v.x * v.x + v.y * v.y + v.z * v.z + v.w * v.w;
        }
        __syncthreads();
        if (active) {
            const float4* q4 = (const float4*)(qs + c * GPAD);
            const float4* k4 = (const float4*)(ks + d * GPAD);
            #pragma unroll 8
            for (int p = 0; p < GCH / 4; p++) {
                float4 qv = q4[p], kv = k4[p];
                acc += qv.x * kv.x + qv.y * kv.y + qv.z * kv.z + qv.w * kv.w;
            }
        }
        __syncthreads();
    }
    if (active) gp[((long long)seg * 16 + bh) * 648 + tid] = acc;

    // flush fused sumsq
    {
        int jj = 0;
        for (int i = tid; i < 51 * (GCH / 4); i += 672, jj++) {
            int row = i / (GCH / 4);
            atomicAdd(&red_s[row], sqacc[jj]);
        }
    }
    __syncthreads();
    if (tid < 51) {
        int row = tid;
        int idx;
        if (row < 24)       idx = b * 204 + h * 24 + row;
        else if (row < 27)  idx = b * 204 + 192 + h * 3 + (row - 24);
        else                idx = b * 204 + 96 + h * 24 + (row - 27);
        atomicAdd(&ss[idx], red_s[row]);
    }
}

// ---------------- attn softmax + fold proj_out -> M[b] (bf16 split) ----------------
__global__ void attnm_kernel(const float* __restrict__ gp, const float* __restrict__ ss,
                             const float* __restrict__ temp, const float* __restrict__ projw,
                             __nv_bfloat16* __restrict__ Mh, __nv_bfloat16* __restrict__ Ml) {
    int b = blockIdx.x;
    __shared__ float attn_s[4][27][24];
    int tid = threadIdx.x;
    if (tid < 108) {
        int h = tid / 27, c = tid % 27;
        float ssq = (c < 24) ? ss[b * 204 + h * 24 + c]
                             : ss[b * 204 + 192 + h * 3 + (c - 24)];
        float nq = fmaxf(sqrtf(ssq), 1e-12f);
        float t = temp[h];
        float row[24];
        #pragma unroll
        for (int d = 0; d < 24; d++) {
            float g = 0.f;
            for (int s = 0; s < NSEG; s++)
                g += gp[((long long)s * 16 + b * 4 + h) * 648 + c * 24 + d];
            float nk = fmaxf(sqrtf(ss[b * 204 + 96 + h * 24 + d]), 1e-12f);
            row[d] = g * t / (nq * nk);
        }
        float mx = row[0];
        #pragma unroll
        for (int d = 1; d < 24; d++) mx = fmaxf(mx, row[d]);
        float sum = 0.f;
        #pragma unroll
        for (int d = 0; d < 24; d++) { row[d] = expf(row[d] - mx); sum += row[d]; }
        float inv = 1.f / sum;
        #pragma unroll
        for (int d = 0; d < 24; d++) attn_s[h][c][d] = row[d] * inv;
    }
    __syncthreads();
    for (int e = tid; e < 96 * 96; e += blockDim.x) {
        int o = e / 96, col = e % 96;
        int h = col / 24, d = col % 24;
        float s = 0.f;
        #pragma unroll
        for (int c = 0; c < 27; c++)
            s += projw[o * 108 + h * 27 + c] * attn_s[h][c][d];
        bsplit(s, Mh[b * 9216 + e], Ml[b * 9216 + e]);
    }
}

// ---------------- launch ----------------
extern "C" void kernel_launch(void* const* d_in, const int* in_sizes, int n_in,
                              void* d_out, int out_size) {
    const float* x           = (const float*)d_in[0];
    const float* svp_fea     = (const float*)d_in[1];
    const float* n1w         = (const float*)d_in[2];
    const float* n1b         = (const float*)d_in[3];
    const float* qkv_w       = (const float*)d_in[4];
    const float* qkv_dw_w    = (const float*)d_in[5];
    const float* svp_w       = (const float*)d_in[6];
    const float* temperature = (const float*)d_in[7];
    const float* proj_out_w  = (const float*)d_in[8];
    const float* n2w         = (const float*)d_in[9];
    const float* n2b         = (const float*)d_in[10];
    const float* ffn1_w      = (const float*)d_in[11];
    const float* ffn2_w      = (const float*)d_in[12];
    const float* ffn_out_w   = (const float*)d_in[13];
    float* out = (float*)d_out;

    float *qkvd, *svpq, *mu, *rs, *ss, *gp, *bq, *bg;
    __nv_bfloat16 *qkv, *Mh, *Ml, *Aqh, *Aql, *Agh, *Agl, *Fh, *Fl;
    cudaGetSymbolAddress((void**)&qkv,  g_qkv);
    cudaGetSymbolAddress((void**)&qkvd, g_qkvd);
    cudaGetSymbolAddress((void**)&svpq, g_svpq);
    cudaGetSymbolAddress((void**)&mu,   g_mu);
    cudaGetSymbolAddress((void**)&rs,   g_rs);
    cudaGetSymbolAddress((void**)&ss,   g_ss);
    cudaGetSymbolAddress((void**)&gp,   g_gp);
    cudaGetSymbolAddress((void**)&Mh,   g_Mh);
    cudaGetSymbolAddress((void**)&Ml,   g_Ml);
    cudaGetSymbolAddress((void**)&Aqh,  g_Aqh);
    cudaGetSymbolAddress((void**)&Aql,  g_Aql);
    cudaGetSymbolAddress((void**)&bq,   g_bq);
    cudaGetSymbolAddress((void**)&Agh,  g_Agh);
    cudaGetSymbolAddress((void**)&Agl,  g_Agl);
    cudaGetSymbolAddress((void**)&bg,   g_bg);
    cudaGetSymbolAddress((void**)&Fh,   g_Fh);
    cudaGetSymbolAddress((void**)&Fl,   g_Fl);

    const int GEMM_SMEM = 4 * 2 * 32 * 136 * 2;   // 69632 bytes
    cudaFuncSetAttribute(gemm_t<96, 1, 1, 0, 0, 1, 0>, cudaFuncAttributeMaxDynamicSharedMemorySize, GEMM_SMEM);
    cudaFuncSetAttribute(gemm_t<96, 0, 0, 1, 1, 0, 0>, cudaFuncAttributeMaxDynamicSharedMemorySize, GEMM_SMEM);
    cudaFuncSetAttribute(gemm_t<128, 2, 1, 0, 0, 1, 0>, cudaFuncAttributeMaxDynamicSharedMemorySize, GEMM_SMEM);
    cudaFuncSetAttribute(gemm_t<96, 0, 0, 1, 0, 0, 1>, cudaFuncAttributeMaxDynamicSharedMemorySize, GEMM_SMEM);

    const int pixBlocks = (BATCH * HW + 255) / 256;

    // 0. fold LN weights into split-bf16 A matrices; zero ss
    prep_kernel<<<897, 96>>>(qkv_w, n1w, n1b, ffn1_w, ffn2_w, n2w, n2b, ffn_out_w, ss);
    // 1. LN1 stats
    ln_stats<<<pixBlocks, 256>>>(x, mu, rs);
    // 2. qkv = Aq @ LN(x) + bq -> bf16
    gemm_t<96, 1, 1, 0, 0, 1, 0><<<dim3(512, 3, BATCH), 192, GEMM_SMEM>>>(Aqh, Aql, x, nullptr, qkv,
        bq, mu, rs, nullptr, nullptr, 288, 96, 96, 0, 96LL * HW, 0, 288LL * HW);
    // 3. depthwise 3x3 (bf16 in, fp32 out)
    dwconv3<<<dim3(8, 8, BATCH * 288), 256>>>(qkv, qkv_dw_w, qkvd);
    // 4. svp_q
    svp_kernel<<<pixBlocks, 256>>>(svp_fea, svp_w, svpq);
    // 5. Gram partials + fused sumsq
    gram_kernel<<<dim3(NSEG, 16), 672>>>(qkvd, svpq, gp, ss);
    // 6. softmax + fold proj_out -> M[b]
    attnm_kernel<<<BATCH, 128>>>(gp, ss, temperature, proj_out_w, Mh, Ml);
    // 7. x2 = x + M_b @ v -> out (fp32), fused LN2 stats
    gemm_t<96, 0, 0, 1, 1, 0, 0><<<dim3(512, 1, BATCH), 192, GEMM_SMEM>>>(Mh, Ml, qkvd + 192LL * HW, x, out,
        nullptr, nullptr, nullptr, mu, rs, 96, 96, 96, 9216, 288LL * HW, 96LL * HW, 96LL * HW);
    // 8. interleaved ffn1/ffn2 GEMM + fused dual-gate -> g (bf16, in qkv buffer)
    gemm_t<128, 2, 1, 0, 0, 1, 0><<<dim3(512, 4, BATCH), 256, GEMM_SMEM>>>(Agh, Agl, out, nullptr, qkv,
        bg, mu, rs, nullptr, nullptr, 512, 96, 96, 0, 96LL * HW, 0, 288LL * HW);
    // 9. out = out + ffn_out_w @ g   (B exact bf16 -> 2-term MMA)
    gemm_t<96, 0, 0, 1, 0, 0, 1><<<dim3(512, 1, BATCH), 192, GEMM_SMEM>>>(Fh, Fl, qkv, out, out,
        nullptr, nullptr, nullptr, nullptr, nullptr, 96, 255, 256, 0, 288LL * HW, 96LL * HW, 96LL * HW);
}

// round 15
// speedup vs baseline: 1.2408x; 1.0351x over previous
#include <cuda_runtime.h>
#include <cuda_bf16.h>
#include <math.h>
#include <stdint.h>

#define HW 65536
#define BATCH 4
#define NSEG 32
#define GCH 128
#define GPAD 140

// ---------------- static scratch ----------------
__device__ __nv_bfloat16 g_qkv [(size_t)BATCH * 288 * HW]; // qkv pre-dwconv (bf16); later gated FFN 'g' (bf16)
__device__ __nv_bfloat16 g_qkvd[(size_t)BATCH * 288 * HW]; // qkv post-dwconv (q|k|v) bf16
__device__ float g_svpq[(size_t)BATCH * 12  * HW];          // svp_q (fp32)
__device__ float g_mu  [(size_t)BATCH * HW];
__device__ float g_rs  [(size_t)BATCH * HW];
__device__ float g_ss  [BATCH * 204];
__device__ float g_gp  [NSEG * 16 * 648];
__device__ __nv_bfloat16 g_Mh [BATCH * 96 * 96];
__device__ __nv_bfloat16 g_Ml [BATCH * 96 * 96];
__device__ __nv_bfloat16 g_Aqh[288 * 96];
__device__ __nv_bfloat16 g_Aql[288 * 96];
__device__ float g_bq  [288];
__device__ __nv_bfloat16 g_Agh[512 * 96];
__device__ __nv_bfloat16 g_Agl[512 * 96];
__device__ float g_bg  [512];
__device__ __nv_bfloat16 g_Fh [96 * 256];
__device__ __nv_bfloat16 g_Fl [96 * 256];

// ---------------- helpers ----------------
__device__ __forceinline__ void bsplit(float v, __nv_bfloat16& h, __nv_bfloat16& l) {
    h = __float2bfloat16(v);
    l = __float2bfloat16(v - __bfloat162float(h));
}
__device__ __forceinline__ void split2(float a, float b, uint32_t& h, uint32_t& l) {
    __nv_bfloat16 ha = __float2bfloat16(a), hb = __float2bfloat16(b);
    __nv_bfloat16 la = __float2bfloat16(a - __bfloat162float(ha));
    __nv_bfloat16 lb = __float2bfloat16(b - __bfloat162float(hb));
    __nv_bfloat162 hv(ha, hb), lv(la, lb);
    h = *(uint32_t*)&hv; l = *(uint32_t*)&lv;
}
__device__ __forceinline__ uint32_t s2u(const void* p) {
    return (uint32_t)__cvta_generic_to_shared(p);
}
__device__ __forceinline__ void ldsm4t(uint32_t* r, uint32_t addr) {
    asm volatile("ldmatrix.sync.aligned.m8n8.x4.trans.shared.b16 {%0,%1,%2,%3}, [%4];"
        : "=r"(r[0]), "=r"(r[1]), "=r"(r[2]), "=r"(r[3]) : "r"(addr));
}
__device__ __forceinline__ void mma_bf16(float* d, const uint32_t* a, const uint32_t* b) {
    asm volatile("mma.sync.aligned.m16n8k16.row.col.f32.bf16.bf16.f32 "
        "{%0,%1,%2,%3}, {%4,%5,%6,%7}, {%8,%9}, {%0,%1,%2,%3};"
        : "+f"(d[0]), "+f"(d[1]), "+f"(d[2]), "+f"(d[3])
        : "r"(a[0]), "r"(a[1]), "r"(a[2]), "r"(a[3]), "r"(b[0]), "r"(b[1]));
}
__device__ __forceinline__ float gatef(float a, float bb) {
    float sig = 1.f / (1.f + expf(-bb));
    float gel = 0.5f * a * (1.f + erff(a * 0.70710678118654752f));
    return a * sig + bb * gel;
}
__device__ __forceinline__ float4 bf4_to_f4(uint2 u) {
    __nv_bfloat162 p0 = *(__nv_bfloat162*)&u.x;
    __nv_bfloat162 p1 = *(__nv_bfloat162*)&u.y;
    return make_float4(__low2float(p0), __high2float(p0),
                       __low2float(p1), __high2float(p1));
}

// ---------------- prep: fold LN weights, split to bf16 hi/lo, zero ss ----------------
__global__ void prep_kernel(const float* __restrict__ qkv_w,
                            const float* __restrict__ n1w, const float* __restrict__ n1b,
                            const float* __restrict__ ffn1_w, const float* __restrict__ ffn2_w,
                            const float* __restrict__ n2w, const float* __restrict__ n2b,
                            const float* __restrict__ ffn_out_w, float* __restrict__ ss) {
    int r = blockIdx.x;
    int k = threadIdx.x;  // 0..95
    __shared__ float red[96];
    if (r < 288) {
        float wv = qkv_w[r * 96 + k];
        bsplit(wv * n1w[k], g_Aqh[r * 96 + k], g_Aql[r * 96 + k]);
        red[k] = wv * n1b[k];
        __syncthreads();
        if (k == 0) { float s = 0.f; for (int j = 0; j < 96; j++) s += red[j]; g_bq[r] = s; }
    } else if (r < 800) {
        int c = r - 288;                  // 0..511
        int T = c >> 4, wi = c & 15;
        int g = T * 8 + (wi & 7);
        bool valid = (g < 255);
        const float* W = (wi < 8) ? ffn1_w : ffn2_w;
        float wv = valid ? W[g * 96 + k] : 0.f;
        bsplit(wv * n2w[k], g_Agh[c * 96 + k], g_Agl[c * 96 + k]);
        red[k] = wv * n2b[k];
        __syncthreads();
        if (k == 0) {
            float s = 0.f; for (int j = 0; j < 96; j++) s += red[j];
            if (valid) g_bg[(wi < 8 ? 0 : 256) + g] = s;
        }
    } else if (r < 896) {
        int o = r - 800;                  // 0..95
        for (int kk = k; kk < 256; kk += 96) {
            float v = (kk < 255) ? ffn_out_w[o * 255 + kk] : 0.f;
            bsplit(v, g_Fh[o * 256 + kk], g_Fl[o * 256 + kk]);
        }
    } else {
        for (int j = k; j < BATCH * 204; j += 96) ss[j] = 0.f;
    }
}

// ---------------- LN stats (LN1 only; LN2 fused into gemm epilogue) ----------------
__global__ void ln_stats(const float* __restrict__ x, float* __restrict__ mu,
                         float* __restrict__ rs) {
    int i = blockIdx.x * blockDim.x + threadIdx.x;
    if (i >= BATCH * HW) return;
    int b = i >> 16, pix = i & 65535;
    const float* xp = x + (long long)b * 96 * HW + pix;
    float sum = 0.f, sq = 0.f;
    #pragma unroll 8
    for (int c = 0; c < 96; c++) {
        float v = xp[(long long)c * HW];
        sum += v; sq += v * v;
    }
    float m = sum * (1.f / 96.f);
    float var = sq * (1.f / 96.f) - m * m;
    mu[i] = m;
    rs[i] = rsqrtf(var + 1e-5f);
}

// ---------------- tensor-core GEMM: C[M,65536]=A[M,K]@B, split-bf16 ----------------
// BM in {96,128}, BN=128, BK=32, NT=2*BM threads. k-major smem, trans ldmatrix.
// EPI: 0 plain(+RESID), 1 +bias, 2 dual-gate. STATS: fused LN stats (gridDim.y==1, M=96).
// OBF16: C is bf16.  BEXACT: B is bf16 (exact) -> 2-term MMA, no Bsl.
template <int BM, int EPI, int LN, int RESID, int STATS, int OBF16, int BEXACT>
__global__ __launch_bounds__(2 * BM) void gemm_t(
    const __nv_bfloat16* __restrict__ Ah, const __nv_bfloat16* __restrict__ Al,
    const void* __restrict__ Bv, const float* __restrict__ R, void* __restrict__ Cv,
    const float* __restrict__ bias,
    const float* __restrict__ mu, const float* __restrict__ rs,
    float* __restrict__ muo, float* __restrict__ rso,
    int M, int K, int Kpad,
    long long sA, long long sB, long long sR, long long sC)
{
    constexpr int NT = 2 * BM;
    constexpr int NW = NT / 32;                    // warps: 8 or 6
    constexpr int NBJ = (32 + NW - 1) / NW;        // B k-row sweeps

    extern __shared__ __align__(16) char smem_raw[];
    __nv_bfloat16* Ash = (__nv_bfloat16*)smem_raw;       // [2][32][136]
    __nv_bfloat16* Asl = Ash + 2 * 4352;
    __nv_bfloat16* Bsh = Asl + 2 * 4352;
    __nv_bfloat16* Bsl = Bsh + 2 * 4352;

    Ah += (long long)blockIdx.z * sA;
    Al += (long long)blockIdx.z * sA;
    const float*         Bf = (const float*)Bv         + (long long)blockIdx.z * sB;
    const __nv_bfloat16* Bb = (const __nv_bfloat16*)Bv + (long long)blockIdx.z * sB;
    float*         Cf = (float*)Cv         + (long long)blockIdx.z * sC;
    __nv_bfloat16* Cb = (__nv_bfloat16*)Cv + (long long)blockIdx.z * sC;
    if (RESID) R += (long long)blockIdx.z * sR;
    if (LN) { mu += (long long)blockIdx.z * HW; rs += (long long)blockIdx.z * HW; }

    const int m_base = blockIdx.y * BM;
    const int n_base = blockIdx.x * 128;
    const int tid  = threadIdx.x;
    const int lane = tid & 31;
    const int warp = tid >> 5;
    const int wm = warp >> 1, wn = warp & 1;

    // loader coords
    const int bcol = (tid & 31) * 4;   // B col (fixed per thread)
    const int bk0  = warp;             // B k-row base (+NW*j)
    const int am   = tid % BM;         // A m (fixed)
    const int akc0 = tid / BM;         // A k-chunk base (0/1), chunks akc0+2j

    float4 m4, r4;
    if (LN) {
        m4 = *(const float4*)(mu + n_base + bcol);
        r4 = *(const float4*)(rs + n_base + bcol);
    }

    float acc[2][8][4];
    #pragma unroll
    for (int i = 0; i < 2; i++)
        #pragma unroll
        for (int j = 0; j < 8; j++)
            #pragma unroll
            for (int q = 0; q < 4; q++) acc[i][j][q] = 0.f;

    const int nst = (K + 31) >> 5;
    uint4 rgah[2], rgal[2];
    float4 rgb[NBJ];
    uint2 rbex[NBJ];

    // ldmatrix lane-derived offsets
    const int a_row = (lane & 7) + ((lane >> 4) & 1) * 8;
    const int a_col = ((lane >> 3) & 1) * 8;
    const int b_row = (lane & 7) + ((lane >> 3) & 1) * 8;
    const int b_col = ((lane >> 4) & 1) * 8 + wn * 64;

    auto fetch = [&](int kg) {
        #pragma unroll
        for (int j = 0; j < 2; j++) {
            int kc = akc0 + 2 * j;
            int grow = m_base + am;
            if (grow < M) {
                long long off = (long long)grow * Kpad + kg + kc * 8;
                rgah[j] = *(const uint4*)(Ah + off);
                rgal[j] = *(const uint4*)(Al + off);
            } else {
                rgah[j] = make_uint4(0, 0, 0, 0);
                rgal[j] = make_uint4(0, 0, 0, 0);
            }
        }
        #pragma unroll
        for (int j = 0; j < NBJ; j++) {
            int kr = bk0 + NW * j;
            if (kr < 32) {
                int kb = kg + kr;
                if (BEXACT) {
                    rbex[j] = (kb < K) ? *(const uint2*)(Bb + (long long)kb * HW + n_base + bcol)
                                       : make_uint2(0, 0);
                } else {
                    if (kb < K) {
                        float4 v = *(const float4*)(Bf + (long long)kb * HW + n_base + bcol);
                        if (LN) {
                            v.x = (v.x - m4.x) * r4.x; v.y = (v.y - m4.y) * r4.y;
                            v.z = (v.z - m4.z) * r4.z; v.w = (v.w - m4.w) * r4.w;
                        }
                        rgb[j] = v;
                    } else {
                        rgb[j] = make_float4(0.f, 0.f, 0.f, 0.f);
                    }
                }
            }
        }
    };
    auto stash = [&](int buf) {
        int base = buf * 4352;
        #pragma unroll
        for (int j = 0; j < 2; j++) {
            int kb = (akc0 + 2 * j) * 8;
            const __nv_bfloat16* ph = (const __nv_bfloat16*)&rgah[j];
            const __nv_bfloat16* pl = (const __nv_bfloat16*)&rgal[j];
            #pragma unroll
            for (int rr = 0; rr < 8; rr++) {
                Ash[base + (kb + rr) * 136 + am] = ph[rr];
                Asl[base + (kb + rr) * 136 + am] = pl[rr];
            }
        }
        #pragma unroll
        for (int j = 0; j < NBJ; j++) {
            int kr = bk0 + NW * j;
            if (kr < 32) {
                if (BEXACT) {
                    *(uint2*)&Bsh[base + kr * 136 + bcol] = rbex[j];
                } else {
                    uint2 h2, l2;
                    split2(rgb[j].x, rgb[j].y, h2.x, l2.x);
                    split2(rgb[j].z, rgb[j].w, h2.y, l2.y);
                    *(uint2*)&Bsh[base + kr * 136 + bcol] = h2;
                    *(uint2*)&Bsl[base + kr * 136 + bcol] = l2;
                }
            }
        }
    };

    fetch(0);
    stash(0);
    __syncthreads();

    for (int s = 0; s < nst; s++) {
        int buf = s & 1;
        if (s + 1 < nst) fetch((s + 1) * 32);

        int base = buf * 4352;
        #pragma unroll
        for (int step = 0; step < 2; step++) {
            int k0 = step * 16;
            uint32_t ah[2][4], al[2][4];
            #pragma unroll
            for (int i = 0; i < 2; i++) {
                int col = wm * 32 + i * 16 + a_col;
                int off = base + (k0 + a_row) * 136 + col;
                ldsm4t(ah[i], s2u(&Ash[off]));
                ldsm4t(al[i], s2u(&Asl[off]));
            }
            uint32_t bh[4][4], bl[4][4];
            #pragma unroll
            for (int jp = 0; jp < 4; jp++) {
                int col = b_col + jp * 16;
                int off = base + (k0 + b_row) * 136 + col;
                ldsm4t(bh[jp], s2u(&Bsh[off]));
                if (!BEXACT) ldsm4t(bl[jp], s2u(&Bsl[off]));
            }
            #pragma unroll
            for (int i = 0; i < 2; i++) {
                #pragma unroll
                for (int j = 0; j < 8; j++) {
                    int jp = j >> 1;
                    const uint32_t* bhp = (j & 1) ? bh[jp] + 2 : bh[jp];
                    mma_bf16(acc[i][j], ah[i], bhp);
                    if (!BEXACT) {
                        const uint32_t* blp = (j & 1) ? bl[jp] + 2 : bl[jp];
                        mma_bf16(acc[i][j], ah[i], blp);
                    }
                    mma_bf16(acc[i][j], al[i], bhp);
                }
            }
        }
        if (s + 1 < nst) stash(buf ^ 1);
        __syncthreads();
    }

    // ---------------- epilogue ----------------
    float ls[16], ls2[16];
    if (STATS) {
        #pragma unroll
        for (int e = 0; e < 16; e++) { ls[e] = 0.f; ls2[e] = 0.f; }
    }

    if (EPI == 2) {
        #pragma unroll
        for (int i = 0; i < 2; i++) {
            int T = (m_base >> 4) + wm * 2 + i;
            int g = T * 8 + (lane >> 2);
            if (g < 255) {
                float b1 = bias[g], b2 = bias[256 + g];
                #pragma unroll
                for (int j = 0; j < 8; j++) {
                    int col = n_base + wn * 64 + j * 8 + 2 * (lane & 3);
                    float vx = gatef(acc[i][j][0] + b1, acc[i][j][2] + b2);
                    float vy = gatef(acc[i][j][1] + b1, acc[i][j][3] + b2);
                    if (OBF16) {
                        __nv_bfloat162 bv2(__float2bfloat16(vx), __float2bfloat16(vy));
                        *(__nv_bfloat162*)(Cb + (long long)g * HW + col) = bv2;
                    } else {
                        *(float2*)(Cf + (long long)g * HW + col) = make_float2(vx, vy);
                    }
                }
            }
        }
    } else {
        #pragma unroll
        for (int i = 0; i < 2; i++) {
            int r0 = m_base + wm * 32 + i * 16 + (lane >> 2);
            int r1 = r0 + 8;
            float bv0 = 0.f, bv1 = 0.f;
            if (EPI == 1) {
                if (r0 < M) bv0 = bias[r0];
                if (r1 < M) bv1 = bias[r1];
            }
            #pragma unroll
            for (int j = 0; j < 8; j++) {
                int col = n_base + wn * 64 + j * 8 + 2 * (lane & 3);
                #pragma unroll
                for (int half = 0; half < 2; half++) {
                    int rr = half ? r1 : r0;
                    if (rr >= M) continue;
                    float bv = half ? bv1 : bv0;
                    float vx = acc[i][j][half * 2 + 0] + bv;
                    float vy = acc[i][j][half * 2 + 1] + bv;
                    long long o = (long long)rr * HW + col;
                    if (RESID) {
                        float2 rv = *(const float2*)(R + o);
                        vx += rv.x; vy += rv.y;
                    }
                    if (OBF16) {
                        __nv_bfloat162 bv2(__float2bfloat16(vx), __float2bfloat16(vy));
                        *(__nv_bfloat162*)(Cb + o) = bv2;
                    } else {
                        *(float2*)(Cf + o) = make_float2(vx, vy);
                    }
                    if (STATS) {
                        ls[2 * j] += vx; ls[2 * j + 1] += vy;
                        ls2[2 * j] += vx * vx; ls2[2 * j + 1] += vy * vy;
                    }
                }
            }
        }
    }

    if (STATS) {
        __syncthreads();
        float* sstat = (float*)smem_raw;   // [0..127]=sum, [128..255]=sumsq
        for (int t = tid; t < 256; t += NT) sstat[t] = 0.f;
        __syncthreads();
        if (wm < 3) {
            #pragma unroll
            for (int o = 16; o >= 4; o >>= 1) {
                #pragma unroll
                for (int e = 0; e < 16; e++) {
                    ls[e]  += __shfl_down_sync(0xffffffffu, ls[e],  o);
                    ls2[e] += __shfl_down_sync(0xffffffffu, ls2[e], o);
                }
            }
            if (lane < 4) {
                #pragma unroll
                for (int e = 0; e < 16; e++) {
                    int j = e >> 1, q = e & 1;
                    int nl = wn * 64 + j * 8 + 2 * lane + q;
                    atomicAdd(&sstat[nl], ls[e]);
                    atomicAdd(&sstat[128 + nl], ls2[e]);
                }
            }
        }
        __syncthreads();
        if (tid < 128) {
            float sm = sstat[tid] * (1.f / 96.f);
            float sq = sstat[tid + 128] * (1.f / 96.f);
            float var = sq - sm * sm;
            muo[(long long)blockIdx.z * HW + n_base + tid] = sm;
            rso[(long long)blockIdx.z * HW + n_base + tid] = rsqrtf(var + 1e-5f);
        }
    }
}

// ---------------- 3x3 depthwise conv: 32x32 tile, bf16 in / bf16 out ----------------
__global__ __launch_bounds__(256) void dwconv3(const __nv_bfloat16* __restrict__ in,
                                               const float* __restrict__ w,
                                               __nv_bfloat16* __restrict__ out) {
    int zc = blockIdx.z;
    int c = zc % 288;
    const __nv_bfloat16* src = in + (long long)zc * HW;
    __nv_bfloat16* dst = out + (long long)zc * HW;
    int ox = blockIdx.x * 32, oy = blockIdx.y * 32;
    __shared__ float s[34][40];    // col q*4 <-> gx = ox-4+q*4 ; needed cols 3..36
    int tid = threadIdx.x;
    #pragma unroll
    for (int j = 0; j < 2; j++) {
        int sl = tid + j * 256;
        if (sl < 340) {
            int r = sl / 10, q = sl - r * 10;
            int gy = oy + r - 1, gx = ox - 4 + q * 4;
            float4 v = make_float4(0.f, 0.f, 0.f, 0.f);
            if (gy >= 0 && gy < 256 && gx >= 0 && gx <= 252) {
                uint2 u = *(const uint2*)(src + gy * 256 + gx);
                v = bf4_to_f4(u);
            }
            *(float4*)&s[r][q * 4] = v;
        }
    }
    __syncthreads();
    const float* wc = w + c * 9;
    float w00 = wc[0], w01 = wc[1], w02 = wc[2];
    float w10 = wc[3], w11 = wc[4], w12 = wc[5];
    float w20 = wc[6], w21 = wc[7], w22 = wc[8];
    int row  = tid >> 3;           // 0..31
    int colq = (tid & 7) * 4;      // 0..28
    float v[3][6];
    #pragma unroll
    for (int dr = 0; dr < 3; dr++) {
        float4 m = *(const float4*)&s[row + dr][colq + 4];
        v[dr][0] = s[row + dr][colq + 3];
        v[dr][1] = m.x; v[dr][2] = m.y; v[dr][3] = m.z; v[dr][4] = m.w;
        v[dr][5] = s[row + dr][colq + 8];
    }
    float o[4];
    #pragma unroll
    for (int t = 0; t < 4; t++) {
        o[t] = w00 * v[0][t] + w01 * v[0][t + 1] + w02 * v[0][t + 2]
             + w10 * v[1][t] + w11 * v[1][t + 1] + w12 * v[1][t + 2]
             + w20 * v[2][t] + w21 * v[2][t + 1] + w22 * v[2][t + 2];
    }
    __nv_bfloat162 p0(__float2bfloat16(o[0]), __float2bfloat16(o[1]));
    __nv_bfloat162 p1(__float2bfloat16(o[2]), __float2bfloat16(o[3]));
    uint2 u;
    u.x = *(uint32_t*)&p0; u.y = *(uint32_t*)&p1;
    *(uint2*)(dst + (oy + row) * 256 + ox + colq) = u;
}

// ---------------- svp 1x1 conv ----------------
__global__ void svp_kernel(const float* __restrict__ fea, const float* __restrict__ w,
                           float* __restrict__ out) {
    int i = blockIdx.x * blockDim.x + threadIdx.x;
    if (i >= BATCH * HW) return;
    int b = i >> 16, pix = i & 65535;
    const float* f = fea + (long long)b * 3 * HW + pix;
    float f0 = f[0], f1 = f[HW], f2 = f[2 * HW];
    float* o = out + (long long)b * 12 * HW + pix;
    #pragma unroll
    for (int r = 0; r < 12; r++)
        o[(long long)r * HW] = w[r * 3] * f0 + w[r * 3 + 1] * f1 + w[r * 3 + 2] * f2;
}

// ---------------- Gram partials + fused per-row sum of squares ----------------
// qkvd rows are bf16; svpq rows are fp32. All converted to fp32 in smem.
__global__ __launch_bounds__(672) void gram_kernel(const __nv_bfloat16* __restrict__ qkvd,
                                                   const float* __restrict__ svpq,
                                                   float* __restrict__ gp,
                                                   float* __restrict__ ss) {
    __shared__ float qs[27 * GPAD];
    __shared__ float ks[24 * GPAD];
    __shared__ float red_s[51];
    int seg = blockIdx.x;
    int bh  = blockIdx.y;
    int b = bh >> 2, h = bh & 3;
    int tid = threadIdx.x;
    int c = tid / 24, d = tid % 24;
    bool active = tid < 648;
    long long segoff = (long long)seg * (HW / NSEG);
    float acc = 0.f;
    float sqacc[3] = {0.f, 0.f, 0.f};
    if (tid < 51) red_s[tid] = 0.f;

    for (int ch = 0; ch < HW / NSEG; ch += GCH) {
        int jj = 0;
        for (int i = tid; i < 51 * (GCH / 4); i += 672, jj++) {
            int row = i / (GCH / 4), col4 = i % (GCH / 4);
            float4 v;
            float* dstb;
            if (row < 27) {
                if (row < 24) {
                    const __nv_bfloat16* src = qkvd + ((long long)b * 288 + h * 24 + row) * HW;
                    v = bf4_to_f4(*(const uint2*)(src + segoff + ch + col4 * 4));
                } else {
                    const float* src = svpq + ((long long)b * 12 + h * 3 + (row - 24)) * HW;
                    v = *(const float4*)(src + segoff + ch + col4 * 4);
                }
                dstb = qs + row * GPAD;
            } else {
                int rr = row - 27;
                const __nv_bfloat16* src = qkvd + ((long long)b * 288 + 96 + h * 24 + rr) * HW;
                v = bf4_to_f4(*(const uint2*)(src + segoff + ch + col4 * 4));
                dstb = ks + rr * GPAD;
            }
            *(float4*)(dstb + col4 * 4) = v;
            sqacc[jj] += v.x * v.x + v.y * v.y + v.z * v.z + v.w * v.w;
        }
        __syncthreads();
        if (active) {
            const float4* q4 = (const float4*)(qs + c * GPAD);
            const float4* k4 = (const float4*)(ks + d * GPAD);
            #pragma unroll 8
            for (int p = 0; p < GCH / 4; p++) {
                float4 qv = q4[p], kv = k4[p];
                acc += qv.x * kv.x + qv.y * kv.y + qv.z * kv.z + qv.w * kv.w;
            }
        }
        __syncthreads();
    }
    if (active) gp[((long long)seg * 16 + bh) * 648 + tid] = acc;

    // flush fused sumsq
    {
        int jj = 0;
        for (int i = tid; i < 51 * (GCH / 4); i += 672, jj++) {
            int row = i / (GCH / 4);
            atomicAdd(&red_s[row], sqacc[jj]);
        }
    }
    __syncthreads();
    if (tid < 51) {
        int row = tid;
        int idx;
        if (row < 24)       idx = b * 204 + h * 24 + row;
        else if (row < 27)  idx = b * 204 + 192 + h * 3 + (row - 24);
        else                idx = b * 204 + 96 + h * 24 + (row - 27);
        atomicAdd(&ss[idx], red_s[row]);
    }
}

// ---------------- attn softmax + fold proj_out -> M[b] (bf16 split) ----------------
__global__ void attnm_kernel(const float* __restrict__ gp, const float* __restrict__ ss,
                             const float* __restrict__ temp, const float* __restrict__ projw,
                             __nv_bfloat16* __restrict__ Mh, __nv_bfloat16* __restrict__ Ml) {
    int b = blockIdx.x;
    __shared__ float attn_s[4][27][24];
    int tid = threadIdx.x;
    if (tid < 108) {
        int h = tid / 27, c = tid % 27;
        float ssq = (c < 24) ? ss[b * 204 + h * 24 + c]
                             : ss[b * 204 + 192 + h * 3 + (c - 24)];
        float nq = fmaxf(sqrtf(ssq), 1e-12f);
        float t = temp[h];
        float row[24];
        #pragma unroll
        for (int d = 0; d < 24; d++) {
            float g = 0.f;
            for (int s = 0; s < NSEG; s++)
                g += gp[((long long)s * 16 + b * 4 + h) * 648 + c * 24 + d];
            float nk = fmaxf(sqrtf(ss[b * 204 + 96 + h * 24 + d]), 1e-12f);
            row[d] = g * t / (nq * nk);
        }
        float mx = row[0];
        #pragma unroll
        for (int d = 1; d < 24; d++) mx = fmaxf(mx, row[d]);
        float sum = 0.f;
        #pragma unroll
        for (int d = 0; d < 24; d++) { row[d] = expf(row[d] - mx); sum += row[d]; }
        float inv = 1.f / sum;
        #pragma unroll
        for (int d = 0; d < 24; d++) attn_s[h][c][d] = row[d] * inv;
    }
    __syncthreads();
    for (int e = tid; e < 96 * 96; e += blockDim.x) {
        int o = e / 96, col = e % 96;
        int h = col / 24, d = col % 24;
        float s = 0.f;
        #pragma unroll
        for (int c = 0; c < 27; c++)
            s += projw[o * 108 + h * 27 + c] * attn_s[h][c][d];
        bsplit(s, Mh[b * 9216 + e], Ml[b * 9216 + e]);
    }
}

// ---------------- launch ----------------
extern "C" void kernel_launch(void* const* d_in, const int* in_sizes, int n_in,
                              void* d_out, int out_size) {
    const float* x           = (const float*)d_in[0];
    const float* svp_fea     = (const float*)d_in[1];
    const float* n1w         = (const float*)d_in[2];
    const float* n1b         = (const float*)d_in[3];
    const float* qkv_w       = (const float*)d_in[4];
    const float* qkv_dw_w    = (const float*)d_in[5];
    const float* svp_w       = (const float*)d_in[6];
    const float* temperature = (const float*)d_in[7];
    const float* proj_out_w  = (const float*)d_in[8];
    const float* n2w         = (const float*)d_in[9];
    const float* n2b         = (const float*)d_in[10];
    const float* ffn1_w      = (const float*)d_in[11];
    const float* ffn2_w      = (const float*)d_in[12];
    const float* ffn_out_w   = (const float*)d_in[13];
    float* out = (float*)d_out;

    float *svpq, *mu, *rs, *ss, *gp, *bq, *bg;
    __nv_bfloat16 *qkv, *qkvd, *Mh, *Ml, *Aqh, *Aql, *Agh, *Agl, *Fh, *Fl;
    cudaGetSymbolAddress((void**)&qkv,  g_qkv);
    cudaGetSymbolAddress((void**)&qkvd, g_qkvd);
    cudaGetSymbolAddress((void**)&svpq, g_svpq);
    cudaGetSymbolAddress((void**)&mu,   g_mu);
    cudaGetSymbolAddress((void**)&rs,   g_rs);
    cudaGetSymbolAddress((void**)&ss,   g_ss);
    cudaGetSymbolAddress((void**)&gp,   g_gp);
    cudaGetSymbolAddress((void**)&Mh,   g_Mh);
    cudaGetSymbolAddress((void**)&Ml,   g_Ml);
    cudaGetSymbolAddress((void**)&Aqh,  g_Aqh);
    cudaGetSymbolAddress((void**)&Aql,  g_Aql);
    cudaGetSymbolAddress((void**)&bq,   g_bq);
    cudaGetSymbolAddress((void**)&Agh,  g_Agh);
    cudaGetSymbolAddress((void**)&Agl,  g_Agl);
    cudaGetSymbolAddress((void**)&bg,   g_bg);
    cudaGetSymbolAddress((void**)&Fh,   g_Fh);
    cudaGetSymbolAddress((void**)&Fl,   g_Fl);

    const int GEMM_SMEM = 4 * 2 * 32 * 136 * 2;   // 69632 bytes
    cudaFuncSetAttribute(gemm_t<96, 1, 1, 0, 0, 1, 0>, cudaFuncAttributeMaxDynamicSharedMemorySize, GEMM_SMEM);
    cudaFuncSetAttribute(gemm_t<96, 0, 0, 1, 1, 0, 1>, cudaFuncAttributeMaxDynamicSharedMemorySize, GEMM_SMEM);
    cudaFuncSetAttribute(gemm_t<128, 2, 1, 0, 0, 1, 0>, cudaFuncAttributeMaxDynamicSharedMemorySize, GEMM_SMEM);
    cudaFuncSetAttribute(gemm_t<96, 0, 0, 1, 0, 0, 1>, cudaFuncAttributeMaxDynamicSharedMemorySize, GEMM_SMEM);

    const int pixBlocks = (BATCH * HW + 255) / 256;

    // 0. fold LN weights into split-bf16 A matrices; zero ss
    prep_kernel<<<897, 96>>>(qkv_w, n1w, n1b, ffn1_w, ffn2_w, n2w, n2b, ffn_out_w, ss);
    // 1. LN1 stats
    ln_stats<<<pixBlocks, 256>>>(x, mu, rs);
    // 2. qkv = Aq @ LN(x) + bq -> bf16
    gemm_t<96, 1, 1, 0, 0, 1, 0><<<dim3(512, 3, BATCH), 192, GEMM_SMEM>>>(Aqh, Aql, x, nullptr, qkv,
        bq, mu, rs, nullptr, nullptr, 288, 96, 96, 0, 96LL * HW, 0, 288LL * HW);
    // 3. depthwise 3x3 (bf16 in, bf16 out)
    dwconv3<<<dim3(8, 8, BATCH * 288), 256>>>(qkv, qkv_dw_w, qkvd);
    // 4. svp_q
    svp_kernel<<<pixBlocks, 256>>>(svp_fea, svp_w, svpq);
    // 5. Gram partials + fused sumsq (bf16 q/k, fp32 svp)
    gram_kernel<<<dim3(NSEG, 16), 672>>>(qkvd, svpq, gp, ss);
    // 6. softmax + fold proj_out -> M[b]
    attnm_kernel<<<BATCH, 128>>>(gp, ss, temperature, proj_out_w, Mh, Ml);
    // 7. x2 = x + M_b @ v -> out (fp32), fused LN2 stats; v exact bf16 -> 2-term MMA
    gemm_t<96, 0, 0, 1, 1, 0, 1><<<dim3(512, 1, BATCH), 192, GEMM_SMEM>>>(Mh, Ml, qkvd + 192LL * HW, x, out,
        nullptr, nullptr, nullptr, mu, rs, 96, 96, 96, 9216, 288LL * HW, 96LL * HW, 96LL * HW);
    // 8. interleaved ffn1/ffn2 GEMM + fused dual-gate -> g (bf16, in qkv buffer)
    gemm_t<128, 2, 1, 0, 0, 1, 0><<<dim3(512, 4, BATCH), 256, GEMM_SMEM>>>(Agh, Agl, out, nullptr, qkv,
        bg, mu, rs, nullptr, nullptr, 512, 96, 96, 0, 96LL * HW, 0, 288LL * HW);
    // 9. out = out + ffn_out_w @ g   (B exact bf16 -> 2-term MMA)
    gemm_t<96, 0, 0, 1, 0, 0, 1><<<dim3(512, 1, BATCH), 192, GEMM_SMEM>>>(Fh, Fl, qkv, out, out,
        nullptr, nullptr, nullptr, nullptr, nullptr, 96, 255, 256, 0, 288LL * HW, 96LL * HW, 96LL * HW);
}

// round 16
// speedup vs baseline: 1.3627x; 1.0983x over previous
#include <cuda_runtime.h>
#include <cuda_bf16.h>
#include <math.h>
#include <stdint.h>

#define HW 65536
#define BATCH 4
#define NSEG 32
#define GCH 128
#define GPAD 140

// ---------------- static scratch ----------------
__device__ __nv_bfloat16 g_qkv [(size_t)BATCH * 288 * HW]; // qkv pre-dwconv (bf16); later gated FFN 'g' (bf16)
__device__ __nv_bfloat16 g_qkvd[(size_t)BATCH * 288 * HW]; // xn (LN1, first 96 rows) then qkv post-dwconv bf16
__device__ __nv_bfloat16 g_x2n [(size_t)BATCH * 96  * HW]; // normalized LN2(x2) bf16
__device__ float g_svpq[(size_t)BATCH * 12  * HW];          // svp_q (fp32)
__device__ float g_ss  [BATCH * 204];
__device__ float g_gp  [NSEG * 16 * 648];
__device__ __nv_bfloat16 g_Mh [BATCH * 96 * 96];
__device__ __nv_bfloat16 g_Ml [BATCH * 96 * 96];
__device__ __nv_bfloat16 g_Aqh[288 * 96];
__device__ __nv_bfloat16 g_Aql[288 * 96];
__device__ float g_bq  [288];
__device__ __nv_bfloat16 g_Agh[512 * 96];
__device__ __nv_bfloat16 g_Agl[512 * 96];
__device__ float g_bg  [512];
__device__ __nv_bfloat16 g_Fh [96 * 256];
__device__ __nv_bfloat16 g_Fl [96 * 256];

// ---------------- helpers ----------------
__device__ __forceinline__ void bsplit(float v, __nv_bfloat16& h, __nv_bfloat16& l) {
    h = __float2bfloat16(v);
    l = __float2bfloat16(v - __bfloat162float(h));
}
__device__ __forceinline__ uint32_t s2u(const void* p) {
    return (uint32_t)__cvta_generic_to_shared(p);
}
__device__ __forceinline__ void ldsm4t(uint32_t* r, uint32_t addr) {
    asm volatile("ldmatrix.sync.aligned.m8n8.x4.trans.shared.b16 {%0,%1,%2,%3}, [%4];"
        : "=r"(r[0]), "=r"(r[1]), "=r"(r[2]), "=r"(r[3]) : "r"(addr));
}
__device__ __forceinline__ void mma_bf16(float* d, const uint32_t* a, const uint32_t* b) {
    asm volatile("mma.sync.aligned.m16n8k16.row.col.f32.bf16.bf16.f32 "
        "{%0,%1,%2,%3}, {%4,%5,%6,%7}, {%8,%9}, {%0,%1,%2,%3};"
        : "+f"(d[0]), "+f"(d[1]), "+f"(d[2]), "+f"(d[3])
        : "r"(a[0]), "r"(a[1]), "r"(a[2]), "r"(a[3]), "r"(b[0]), "r"(b[1]));
}
__device__ __forceinline__ float gatef(float a, float bb) {
    float sig = 1.f / (1.f + expf(-bb));
    float gel = 0.5f * a * (1.f + erff(a * 0.70710678118654752f));
    return a * sig + bb * gel;
}
__device__ __forceinline__ float4 bf4_to_f4(uint2 u) {
    __nv_bfloat162 p0 = *(__nv_bfloat162*)&u.x;
    __nv_bfloat162 p1 = *(__nv_bfloat162*)&u.y;
    return make_float4(__low2float(p0), __high2float(p0),
                       __low2float(p1), __high2float(p1));
}

// ---------------- prep: fold LN weights, split to bf16 hi/lo, zero ss ----------------
__global__ void prep_kernel(const float* __restrict__ qkv_w,
                            const float* __restrict__ n1w, const float* __restrict__ n1b,
                            const float* __restrict__ ffn1_w, const float* __restrict__ ffn2_w,
                            const float* __restrict__ n2w, const float* __restrict__ n2b,
                            const float* __restrict__ ffn_out_w, float* __restrict__ ss) {
    int r = blockIdx.x;
    int k = threadIdx.x;  // 0..95
    __shared__ float red[96];
    if (r < 288) {
        float wv = qkv_w[r * 96 + k];
        bsplit(wv * n1w[k], g_Aqh[r * 96 + k], g_Aql[r * 96 + k]);
        red[k] = wv * n1b[k];
        __syncthreads();
        if (k == 0) { float s = 0.f; for (int j = 0; j < 96; j++) s += red[j]; g_bq[r] = s; }
    } else if (r < 800) {
        int c = r - 288;                  // 0..511
        int T = c >> 4, wi = c & 15;
        int g = T * 8 + (wi & 7);
        bool valid = (g < 255);
        const float* W = (wi < 8) ? ffn1_w : ffn2_w;
        float wv = valid ? W[g * 96 + k] : 0.f;
        bsplit(wv * n2w[k], g_Agh[c * 96 + k], g_Agl[c * 96 + k]);
        red[k] = wv * n2b[k];
        __syncthreads();
        if (k == 0) {
            float s = 0.f; for (int j = 0; j < 96; j++) s += red[j];
            if (valid) g_bg[(wi < 8 ? 0 : 256) + g] = s;
        }
    } else if (r < 896) {
        int o = r - 800;                  // 0..95
        for (int kk = k; kk < 256; kk += 96) {
            float v = (kk < 255) ? ffn_out_w[o * 255 + kk] : 0.f;
            bsplit(v, g_Fh[o * 256 + kk], g_Fl[o * 256 + kk]);
        }
    } else {
        for (int j = k; j < BATCH * 204; j += 96) ss[j] = 0.f;
    }
}

// ---------------- LN1: normalize to bf16 directly (pair of pixels per thread) ----------------
__global__ void ln_norm(const float* __restrict__ x, __nv_bfloat16* __restrict__ xn) {
    long long i = (long long)blockIdx.x * blockDim.x + threadIdx.x;
    if (i >= (long long)BATCH * HW / 2) return;
    int b = (int)(i / (HW / 2));
    int pix = (int)(i % (HW / 2)) * 2;
    const float* xp = x + (long long)b * 96 * HW + pix;
    float s0 = 0.f, s1 = 0.f, q0 = 0.f, q1 = 0.f;
    #pragma unroll 8
    for (int c = 0; c < 96; c++) {
        float2 v = *(const float2*)(xp + (long long)c * HW);
        s0 += v.x; s1 += v.y; q0 += v.x * v.x; q1 += v.y * v.y;
    }
    float m0 = s0 * (1.f / 96.f), m1 = s1 * (1.f / 96.f);
    float r0 = rsqrtf(q0 * (1.f / 96.f) - m0 * m0 + 1e-5f);
    float r1 = rsqrtf(q1 * (1.f / 96.f) - m1 * m1 + 1e-5f);
    __nv_bfloat16* op = xn + (long long)b * 96 * HW + pix;
    #pragma unroll 8
    for (int c = 0; c < 96; c++) {
        float2 v = *(const float2*)(xp + (long long)c * HW);
        __nv_bfloat162 o(__float2bfloat16((v.x - m0) * r0),
                         __float2bfloat16((v.y - m1) * r1));
        *(__nv_bfloat162*)(op + (long long)c * HW) = o;
    }
}

// ---------------- tensor-core GEMM: C[M,65536]=A[M,K]@B(bf16), 2-term split-A ----------------
// BM in {96,128}, BN=128, BK=32, NT=2*BM threads. k-major smem, trans ldmatrix.
// EPI: 0 plain(+RESID), 1 +bias, 2 dual-gate. STATS: fused LN2 -> writes normalized bf16 xno.
// OBF16: C is bf16. B is ALWAYS exact bf16 (2-term MMA, no B split).
template <int BM, int EPI, int RESID, int STATS, int OBF16>
__global__ __launch_bounds__(2 * BM) void gemm_t(
    const __nv_bfloat16* __restrict__ Ah, const __nv_bfloat16* __restrict__ Al,
    const __nv_bfloat16* __restrict__ B, const float* __restrict__ R, void* __restrict__ Cv,
    const float* __restrict__ bias,
    __nv_bfloat16* __restrict__ xno,
    int M, int K, int Kpad,
    long long sA, long long sB, long long sR, long long sC)
{
    constexpr int NT = 2 * BM;
    constexpr int NW = NT / 32;                    // warps: 8 or 6
    constexpr int NBJ = (32 + NW - 1) / NW;        // B k-row sweeps

    extern __shared__ __align__(16) char smem_raw[];
    __nv_bfloat16* Ash = (__nv_bfloat16*)smem_raw;       // [2][32][136]
    __nv_bfloat16* Asl = Ash + 2 * 4352;
    __nv_bfloat16* Bsh = Asl + 2 * 4352;

    Ah += (long long)blockIdx.z * sA;
    Al += (long long)blockIdx.z * sA;
    B  += (long long)blockIdx.z * sB;
    float*         Cf = (float*)Cv         + (long long)blockIdx.z * sC;
    __nv_bfloat16* Cb = (__nv_bfloat16*)Cv + (long long)blockIdx.z * sC;
    if (RESID) R += (long long)blockIdx.z * sR;
    if (STATS) xno += (long long)blockIdx.z * 96 * HW;

    const int m_base = blockIdx.y * BM;
    const int n_base = blockIdx.x * 128;
    const int tid  = threadIdx.x;
    const int lane = tid & 31;
    const int warp = tid >> 5;
    const int wm = warp >> 1, wn = warp & 1;

    // loader coords
    const int bcol = (tid & 31) * 4;   // B col (fixed per thread)
    const int bk0  = warp;             // B k-row base (+NW*j)
    const int am   = tid % BM;         // A m (fixed)
    const int akc0 = tid / BM;         // A k-chunk base (0/1), chunks akc0+2j

    float acc[2][8][4];
    #pragma unroll
    for (int i = 0; i < 2; i++)
        #pragma unroll
        for (int j = 0; j < 8; j++)
            #pragma unroll
            for (int q = 0; q < 4; q++) acc[i][j][q] = 0.f;

    const int nst = (K + 31) >> 5;
    uint4 rgah[2], rgal[2];
    uint2 rbex[NBJ];

    // ldmatrix lane-derived offsets
    const int a_row = (lane & 7) + ((lane >> 4) & 1) * 8;
    const int a_col = ((lane >> 3) & 1) * 8;
    const int b_row = (lane & 7) + ((lane >> 3) & 1) * 8;
    const int b_col = ((lane >> 4) & 1) * 8 + wn * 64;

    auto fetch = [&](int kg) {
        #pragma unroll
        for (int j = 0; j < 2; j++) {
            int kc = akc0 + 2 * j;
            int grow = m_base + am;
            if (grow < M) {
                long long off = (long long)grow * Kpad + kg + kc * 8;
                rgah[j] = *(const uint4*)(Ah + off);
                rgal[j] = *(const uint4*)(Al + off);
            } else {
                rgah[j] = make_uint4(0, 0, 0, 0);
                rgal[j] = make_uint4(0, 0, 0, 0);
            }
        }
        #pragma unroll
        for (int j = 0; j < NBJ; j++) {
            int kr = bk0 + NW * j;
            if (kr < 32) {
                int kb = kg + kr;
                rbex[j] = (kb < K) ? *(const uint2*)(B + (long long)kb * HW + n_base + bcol)
                                   : make_uint2(0, 0);
            }
        }
    };
    auto stash = [&](int buf) {
        int base = buf * 4352;
        #pragma unroll
        for (int j = 0; j < 2; j++) {
            int kb = (akc0 + 2 * j) * 8;
            const __nv_bfloat16* ph = (const __nv_bfloat16*)&rgah[j];
            const __nv_bfloat16* pl = (const __nv_bfloat16*)&rgal[j];
            #pragma unroll
            for (int rr = 0; rr < 8; rr++) {
                Ash[base + (kb + rr) * 136 + am] = ph[rr];
                Asl[base + (kb + rr) * 136 + am] = pl[rr];
            }
        }
        #pragma unroll
        for (int j = 0; j < NBJ; j++) {
            int kr = bk0 + NW * j;
            if (kr < 32)
                *(uint2*)&Bsh[base + kr * 136 + bcol] = rbex[j];
        }
    };

    fetch(0);
    stash(0);
    __syncthreads();

    for (int s = 0; s < nst; s++) {
        int buf = s & 1;
        if (s + 1 < nst) fetch((s + 1) * 32);

        int base = buf * 4352;
        #pragma unroll
        for (int step = 0; step < 2; step++) {
            int k0 = step * 16;
            uint32_t ah[2][4], al[2][4];
            #pragma unroll
            for (int i = 0; i < 2; i++) {
                int col = wm * 32 + i * 16 + a_col;
                int off = base + (k0 + a_row) * 136 + col;
                ldsm4t(ah[i], s2u(&Ash[off]));
                ldsm4t(al[i], s2u(&Asl[off]));
            }
            uint32_t bh[4][4];
            #pragma unroll
            for (int jp = 0; jp < 4; jp++) {
                int col = b_col + jp * 16;
                int off = base + (k0 + b_row) * 136 + col;
                ldsm4t(bh[jp], s2u(&Bsh[off]));
            }
            #pragma unroll
            for (int i = 0; i < 2; i++) {
                #pragma unroll
                for (int j = 0; j < 8; j++) {
                    int jp = j >> 1;
                    const uint32_t* bhp = (j & 1) ? bh[jp] + 2 : bh[jp];
                    mma_bf16(acc[i][j], ah[i], bhp);
                    mma_bf16(acc[i][j], al[i], bhp);
                }
            }
        }
        if (s + 1 < nst) stash(buf ^ 1);
        __syncthreads();
    }

    // ---------------- epilogue ----------------
    float ls[16], ls2[16];
    if (STATS) {
        #pragma unroll
        for (int e = 0; e < 16; e++) { ls[e] = 0.f; ls2[e] = 0.f; }
    }

    if (EPI == 2) {
        #pragma unroll
        for (int i = 0; i < 2; i++) {
            int T = (m_base >> 4) + wm * 2 + i;
            int g = T * 8 + (lane >> 2);
            if (g < 255) {
                float b1 = bias[g], b2 = bias[256 + g];
                #pragma unroll
                for (int j = 0; j < 8; j++) {
                    int col = n_base + wn * 64 + j * 8 + 2 * (lane & 3);
                    float vx = gatef(acc[i][j][0] + b1, acc[i][j][2] + b2);
                    float vy = gatef(acc[i][j][1] + b1, acc[i][j][3] + b2);
                    if (OBF16) {
                        __nv_bfloat162 bv2(__float2bfloat16(vx), __float2bfloat16(vy));
                        *(__nv_bfloat162*)(Cb + (long long)g * HW + col) = bv2;
                    } else {
                        *(float2*)(Cf + (long long)g * HW + col) = make_float2(vx, vy);
                    }
                }
            }
        }
    } else {
        #pragma unroll
        for (int i = 0; i < 2; i++) {
            int r0 = m_base + wm * 32 + i * 16 + (lane >> 2);
            int r1 = r0 + 8;
            float bv0 = 0.f, bv1 = 0.f;
            if (EPI == 1) {
                if (r0 < M) bv0 = bias[r0];
                if (r1 < M) bv1 = bias[r1];
            }
            #pragma unroll
            for (int j = 0; j < 8; j++) {
                int col = n_base + wn * 64 + j * 8 + 2 * (lane & 3);
                #pragma unroll
                for (int half = 0; half < 2; half++) {
                    int rr = half ? r1 : r0;
                    if (rr >= M) continue;
                    float bv = half ? bv1 : bv0;
                    float vx = acc[i][j][half * 2 + 0] + bv;
                    float vy = acc[i][j][half * 2 + 1] + bv;
                    long long o = (long long)rr * HW + col;
                    if (RESID) {
                        float2 rv = *(const float2*)(R + o);
                        vx += rv.x; vy += rv.y;
                    }
                    if (OBF16) {
                        __nv_bfloat162 bv2(__float2bfloat16(vx), __float2bfloat16(vy));
                        *(__nv_bfloat162*)(Cb + o) = bv2;
                    } else {
                        *(float2*)(Cf + o) = make_float2(vx, vy);
                    }
                    if (STATS) {
                        acc[i][j][half * 2 + 0] = vx;   // retain final values
                        acc[i][j][half * 2 + 1] = vy;
                        ls[2 * j] += vx; ls[2 * j + 1] += vy;
                        ls2[2 * j] += vx * vx; ls2[2 * j + 1] += vy * vy;
                    }
                }
            }
        }
    }

    if (STATS) {
        __syncthreads();
        float* sstat = (float*)smem_raw;   // [0..127]=sum->mu, [128..255]=sumsq->rstd
        for (int t = tid; t < 256; t += NT) sstat[t] = 0.f;
        __syncthreads();
        if (wm < 3) {
            #pragma unroll
            for (int o = 16; o >= 4; o >>= 1) {
                #pragma unroll
                for (int e = 0; e < 16; e++) {
                    ls[e]  += __shfl_down_sync(0xffffffffu, ls[e],  o);
                    ls2[e] += __shfl_down_sync(0xffffffffu, ls2[e], o);
                }
            }
            if (lane < 4) {
                #pragma unroll
                for (int e = 0; e < 16; e++) {
                    int j = e >> 1, q = e & 1;
                    int nl = wn * 64 + j * 8 + 2 * lane + q;
                    atomicAdd(&sstat[nl], ls[e]);
                    atomicAdd(&sstat[128 + nl], ls2[e]);
                }
            }
        }
        __syncthreads();
        if (tid < 128) {
            float sm = sstat[tid] * (1.f / 96.f);
            float sq = sstat[tid + 128] * (1.f / 96.f);
            sstat[tid] = sm;
            sstat[tid + 128] = rsqrtf(sq - sm * sm + 1e-5f);
        }
        __syncthreads();
        // write normalized bf16 x2n from retained register values
        #pragma unroll
        for (int i = 0; i < 2; i++) {
            int r0 = m_base + wm * 32 + i * 16 + (lane >> 2);
            #pragma unroll
            for (int j = 0; j < 8; j++) {
                int col128 = wn * 64 + j * 8 + 2 * (lane & 3);
                float mu0 = sstat[col128],       mu1 = sstat[col128 + 1];
                float rs0 = sstat[128 + col128], rs1 = sstat[129 + col128];
                #pragma unroll
                for (int half = 0; half < 2; half++) {
                    int rr = half ? (r0 + 8) : r0;
                    if (rr >= M) continue;
                    float vx = acc[i][j][half * 2 + 0];
                    float vy = acc[i][j][half * 2 + 1];
                    __nv_bfloat162 o2(__float2bfloat16((vx - mu0) * rs0),
                                      __float2bfloat16((vy - mu1) * rs1));
                    *(__nv_bfloat162*)(xno + (long long)rr * HW + n_base + col128) = o2;
                }
            }
        }
    }
}

// ---------------- 3x3 depthwise conv: 32x32 tile, bf16 in / bf16 out ----------------
__global__ __launch_bounds__(256) void dwconv3(const __nv_bfloat16* __restrict__ in,
                                               const float* __restrict__ w,
                                               __nv_bfloat16* __restrict__ out) {
    int zc = blockIdx.z;
    int c = zc % 288;
    const __nv_bfloat16* src = in + (long long)zc * HW;
    __nv_bfloat16* dst = out + (long long)zc * HW;
    int ox = blockIdx.x * 32, oy = blockIdx.y * 32;
    __shared__ float s[34][40];
    int tid = threadIdx.x;
    #pragma unroll
    for (int j = 0; j < 2; j++) {
        int sl = tid + j * 256;
        if (sl < 340) {
            int r = sl / 10, q = sl - r * 10;
            int gy = oy + r - 1, gx = ox - 4 + q * 4;
            float4 v = make_float4(0.f, 0.f, 0.f, 0.f);
            if (gy >= 0 && gy < 256 && gx >= 0 && gx <= 252) {
                uint2 u = *(const uint2*)(src + gy * 256 + gx);
                v = bf4_to_f4(u);
            }
            *(float4*)&s[r][q * 4] = v;
        }
    }
    __syncthreads();
    const float* wc = w + c * 9;
    float w00 = wc[0], w01 = wc[1], w02 = wc[2];
    float w10 = wc[3], w11 = wc[4], w12 = wc[5];
    float w20 = wc[6], w21 = wc[7], w22 = wc[8];
    int row  = tid >> 3;
    int colq = (tid & 7) * 4;
    float v[3][6];
    #pragma unroll
    for (int dr = 0; dr < 3; dr++) {
        float4 m = *(const float4*)&s[row + dr][colq + 4];
        v[dr][0] = s[row + dr][colq + 3];
        v[dr][1] = m.x; v[dr][2] = m.y; v[dr][3] = m.z; v[dr][4] = m.w;
        v[dr][5] = s[row + dr][colq + 8];
    }
    float o[4];
    #pragma unroll
    for (int t = 0; t < 4; t++) {
        o[t] = w00 * v[0][t] + w01 * v[0][t + 1] + w02 * v[0][t + 2]
             + w10 * v[1][t] + w11 * v[1][t + 1] + w12 * v[1][t + 2]
             + w20 * v[2][t] + w21 * v[2][t + 1] + w22 * v[2][t + 2];
    }
    __nv_bfloat162 p0(__float2bfloat16(o[0]), __float2bfloat16(o[1]));
    __nv_bfloat162 p1(__float2bfloat16(o[2]), __float2bfloat16(o[3]));
    uint2 u;
    u.x = *(uint32_t*)&p0; u.y = *(uint32_t*)&p1;
    *(uint2*)(dst + (oy + row) * 256 + ox + colq) = u;
}

// ---------------- svp 1x1 conv ----------------
__global__ void svp_kernel(const float* __restrict__ fea, const float* __restrict__ w,
                           float* __restrict__ out) {
    int i = blockIdx.x * blockDim.x + threadIdx.x;
    if (i >= BATCH * HW) return;
    int b = i >> 16, pix = i & 65535;
    const float* f = fea + (long long)b * 3 * HW + pix;
    float f0 = f[0], f1 = f[HW], f2 = f[2 * HW];
    float* o = out + (long long)b * 12 * HW + pix;
    #pragma unroll
    for (int r = 0; r < 12; r++)
        o[(long long)r * HW] = w[r * 3] * f0 + w[r * 3 + 1] * f1 + w[r * 3 + 2] * f2;
}

// ---------------- Gram partials + fused per-row sum of squares ----------------
__global__ __launch_bounds__(672) void gram_kernel(const __nv_bfloat16* __restrict__ qkvd,
                                                   const float* __restrict__ svpq,
                                                   float* __restrict__ gp,
                                                   float* __restrict__ ss) {
    __shared__ float qs[27 * GPAD];
    __shared__ float ks[24 * GPAD];
    __shared__ float red_s[51];
    int seg = blockIdx.x;
    int bh  = blockIdx.y;
    int b = bh >> 2, h = bh & 3;
    int tid = threadIdx.x;
    int c = tid / 24, d = tid % 24;
    bool active = tid < 648;
    long long segoff = (long long)seg * (HW / NSEG);
    float acc = 0.f;
    float sqacc[3] = {0.f, 0.f, 0.f};
    if (tid < 51) red_s[tid] = 0.f;

    for (int ch = 0; ch < HW / NSEG; ch += GCH) {
        int jj = 0;
        for (int i = tid; i < 51 * (GCH / 4); i += 672, jj++) {
            int row = i / (GCH / 4), col4 = i % (GCH / 4);
            float4 v;
            float* dstb;
            if (row < 27) {
                if (row < 24) {
                    const __nv_bfloat16* src = qkvd + ((long long)b * 288 + h * 24 + row) * HW;
                    v = bf4_to_f4(*(const uint2*)(src + segoff + ch + col4 * 4));
                } else {
                    const float* src = svpq + ((long long)b * 12 + h * 3 + (row - 24)) * HW;
                    v = *(const float4*)(src + segoff + ch + col4 * 4);
                }
                dstb = qs + row * GPAD;
            } else {
                int rr = row - 27;
                const __nv_bfloat16* src = qkvd + ((long long)b * 288 + 96 + h * 24 + rr) * HW;
                v = bf4_to_f4(*(const uint2*)(src + segoff + ch + col4 * 4));
                dstb = ks + rr * GPAD;
            }
            *(float4*)(dstb + col4 * 4) = v;
            sqacc[jj] += v.x * v.x + v.y * v.y + v.z * v.z + v.w * v.w;
        }
        __syncthreads();
        if (active) {
            const float4* q4 = (const float4*)(qs + c * GPAD);
            const float4* k4 = (const float4*)(ks + d * GPAD);
            #pragma unroll 8
            for (int p = 0; p < GCH / 4; p++) {
                float4 qv = q4[p], kv = k4[p];
                acc += qv.x * kv.x + qv.y * kv.y + qv.z * kv.z + qv.w * kv.w;
            }
        }
        __syncthreads();
    }
    if (active) gp[((long long)seg * 16 + bh) * 648 + tid] = acc;

    {
        int jj = 0;
        for (int i = tid; i < 51 * (GCH / 4); i += 672, jj++) {
            int row = i / (GCH / 4);
            atomicAdd(&red_s[row], sqacc[jj]);
        }
    }
    __syncthreads();
    if (tid < 51) {
        int row = tid;
        int idx;
        if (row < 24)       idx = b * 204 + h * 24 + row;
        else if (row < 27)  idx = b * 204 + 192 + h * 3 + (row - 24);
        else                idx = b * 204 + 96 + h * 24 + (row - 27);
        atomicAdd(&ss[idx], red_s[row]);
    }
}

// ---------------- attn softmax + fold proj_out -> M[b] (bf16 split) ----------------
__global__ void attnm_kernel(const float* __restrict__ gp, const float* __restrict__ ss,
                             const float* __restrict__ temp, const float* __restrict__ projw,
                             __nv_bfloat16* __restrict__ Mh, __nv_bfloat16* __restrict__ Ml) {
    int b = blockIdx.x;
    __shared__ float attn_s[4][27][24];
    int tid = threadIdx.x;
    if (tid < 108) {
        int h = tid / 27, c = tid % 27;
        float ssq = (c < 24) ? ss[b * 204 + h * 24 + c]
                             : ss[b * 204 + 192 + h * 3 + (c - 24)];
        float nq = fmaxf(sqrtf(ssq), 1e-12f);
        float t = temp[h];
        float row[24];
        #pragma unroll
        for (int d = 0; d < 24; d++) {
            float g = 0.f;
            for (int s = 0; s < NSEG; s++)
                g += gp[((long long)s * 16 + b * 4 + h) * 648 + c * 24 + d];
            float nk = fmaxf(sqrtf(ss[b * 204 + 96 + h * 24 + d]), 1e-12f);
            row[d] = g * t / (nq * nk);
        }
        float mx = row[0];
        #pragma unroll
        for (int d = 1; d < 24; d++) mx = fmaxf(mx, row[d]);
        float sum = 0.f;
        #pragma unroll
        for (int d = 0; d < 24; d++) { row[d] = expf(row[d] - mx); sum += row[d]; }
        float inv = 1.f / sum;
        #pragma unroll
        for (int d = 0; d < 24; d++) attn_s[h][c][d] = row[d] * inv;
    }
    __syncthreads();
    for (int e = tid; e < 96 * 96; e += blockDim.x) {
        int o = e / 96, col = e % 96;
        int h = col / 24, d = col % 24;
        float s = 0.f;
        #pragma unroll
        for (int c = 0; c < 27; c++)
            s += projw[o * 108 + h * 27 + c] * attn_s[h][c][d];
        bsplit(s, Mh[b * 9216 + e], Ml[b * 9216 + e]);
    }
}

// ---------------- launch ----------------
extern "C" void kernel_launch(void* const* d_in, const int* in_sizes, int n_in,
                              void* d_out, int out_size) {
    const float* x           = (const float*)d_in[0];
    const float* svp_fea     = (const float*)d_in[1];
    const float* n1w         = (const float*)d_in[2];
    const float* n1b         = (const float*)d_in[3];
    const float* qkv_w       = (const float*)d_in[4];
    const float* qkv_dw_w    = (const float*)d_in[5];
    const float* svp_w       = (const float*)d_in[6];
    const float* temperature = (const float*)d_in[7];
    const float* proj_out_w  = (const float*)d_in[8];
    const float* n2w         = (const float*)d_in[9];
    const float* n2b         = (const float*)d_in[10];
    const float* ffn1_w      = (const float*)d_in[11];
    const float* ffn2_w      = (const float*)d_in[12];
    const float* ffn_out_w   = (const float*)d_in[13];
    float* out = (float*)d_out;

    float *svpq, *ss, *gp, *bq, *bg;
    __nv_bfloat16 *qkv, *qkvd, *x2n, *Mh, *Ml, *Aqh, *Aql, *Agh, *Agl, *Fh, *Fl;
    cudaGetSymbolAddress((void**)&qkv,  g_qkv);
    cudaGetSymbolAddress((void**)&qkvd, g_qkvd);
    cudaGetSymbolAddress((void**)&x2n,  g_x2n);
    cudaGetSymbolAddress((void**)&svpq, g_svpq);
    cudaGetSymbolAddress((void**)&ss,   g_ss);
    cudaGetSymbolAddress((void**)&gp,   g_gp);
    cudaGetSymbolAddress((void**)&Mh,   g_Mh);
    cudaGetSymbolAddress((void**)&Ml,   g_Ml);
    cudaGetSymbolAddress((void**)&Aqh,  g_Aqh);
    cudaGetSymbolAddress((void**)&Aql,  g_Aql);
    cudaGetSymbolAddress((void**)&bq,   g_bq);
    cudaGetSymbolAddress((void**)&Agh,  g_Agh);
    cudaGetSymbolAddress((void**)&Agl,  g_Agl);
    cudaGetSymbolAddress((void**)&bg,   g_bg);
    cudaGetSymbolAddress((void**)&Fh,   g_Fh);
    cudaGetSymbolAddress((void**)&Fl,   g_Fl);

    // xn (LN1 output) aliases qkvd: consumed by gemm2 before dwconv3 writes qkvd.
    __nv_bfloat16* xn = qkvd;

    const int GEMM_SMEM = 3 * 2 * 32 * 136 * 2;   // 52224 bytes (no Bsl)
    cudaFuncSetAttribute(gemm_t<96, 1, 0, 0, 1>, cudaFuncAttributeMaxDynamicSharedMemorySize, GEMM_SMEM);
    cudaFuncSetAttribute(gemm_t<96, 0, 1, 1, 0>, cudaFuncAttributeMaxDynamicSharedMemorySize, GEMM_SMEM);
    cudaFuncSetAttribute(gemm_t<128, 2, 0, 0, 1>, cudaFuncAttributeMaxDynamicSharedMemorySize, GEMM_SMEM);
    cudaFuncSetAttribute(gemm_t<96, 0, 1, 0, 0>, cudaFuncAttributeMaxDynamicSharedMemorySize, GEMM_SMEM);

    const int pixBlocks = (BATCH * HW + 255) / 256;

    // 0. fold LN weights into split-bf16 A matrices; zero ss
    prep_kernel<<<897, 96>>>(qkv_w, n1w, n1b, ffn1_w, ffn2_w, n2w, n2b, ffn_out_w, ss);
    // 1. LN1 -> normalized bf16 xn
    ln_norm<<<(BATCH * HW / 2 + 255) / 256, 256>>>(x, xn);
    // 2. qkv = Aq @ xn + bq -> bf16 (B exact)
    gemm_t<96, 1, 0, 0, 1><<<dim3(512, 3, BATCH), 192, GEMM_SMEM>>>(Aqh, Aql, xn, nullptr, qkv,
        bq, nullptr, 288, 96, 96, 0, 96LL * HW, 0, 288LL * HW);
    // 3. depthwise 3x3 (bf16 in, bf16 out) — overwrites qkvd (xn dead)
    dwconv3<<<dim3(8, 8, BATCH * 288), 256>>>(qkv, qkv_dw_w, qkvd);
    // 4. svp_q
    svp_kernel<<<pixBlocks, 256>>>(svp_fea, svp_w, svpq);
    // 5. Gram partials + fused sumsq
    gram_kernel<<<dim3(NSEG, 16), 672>>>(qkvd, svpq, gp, ss);
    // 6. softmax + fold proj_out -> M[b]
    attnm_kernel<<<BATCH, 128>>>(gp, ss, temperature, proj_out_w, Mh, Ml);
    // 7. x2 = x + M_b @ v -> out (fp32) + fused LN2 -> x2n bf16
    gemm_t<96, 0, 1, 1, 0><<<dim3(512, 1, BATCH), 192, GEMM_SMEM>>>(Mh, Ml, qkvd + 192LL * HW, x, out,
        nullptr, x2n, 96, 96, 96, 9216, 288LL * HW, 96LL * HW, 96LL * HW);
    // 8. interleaved ffn1/ffn2 GEMM on x2n (exact bf16) + fused dual-gate -> g (bf16)
    gemm_t<128, 2, 0, 0, 1><<<dim3(512, 4, BATCH), 256, GEMM_SMEM>>>(Agh, Agl, x2n, nullptr, qkv,
        bg, nullptr, 512, 96, 96, 0, 96LL * HW, 0, 288LL * HW);
    // 9. out = out + ffn_out_w @ g (exact bf16)
    gemm_t<96, 0, 1, 0, 0><<<dim3(512, 1, BATCH), 192, GEMM_SMEM>>>(Fh, Fl, qkv, out, out,
        nullptr, nullptr, 96, 255, 256, 0, 288LL * HW, 96LL * HW, 96LL * HW);
}

// round 17
// speedup vs baseline: 1.6795x; 1.2325x over previous
#include <cuda_runtime.h>
#include <cuda_bf16.h>
#include <math.h>
#include <stdint.h>

#define HW 65536
#define BATCH 4
#define NSEG 32
#define GCH 128
#define GPAD 140

// ---------------- static scratch ----------------
__device__ __nv_bfloat16 g_qkv [(size_t)BATCH * 288 * HW]; // qkv pre-dwconv (bf16); later gated FFN 'g' (bf16)
__device__ __nv_bfloat16 g_qkvd[(size_t)BATCH * 288 * HW]; // xn (LN1) then qkv post-dwconv bf16
__device__ __nv_bfloat16 g_x2n [(size_t)BATCH * 96  * HW]; // normalized LN2(x2) bf16
__device__ __nv_bfloat16 g_svpq[(size_t)BATCH * 12  * HW]; // svp_q bf16
__device__ float g_ss  [BATCH * 204];
__device__ float g_gp  [NSEG * 16 * 648];
__device__ __nv_bfloat16 g_Mh [BATCH * 96 * 96];
__device__ __nv_bfloat16 g_Aqh[288 * 96];
__device__ float g_bq  [288];
__device__ __nv_bfloat16 g_Agh[512 * 96];
__device__ float g_bg  [512];
__device__ __nv_bfloat16 g_Fh [96 * 256];

// ---------------- helpers ----------------
__device__ __forceinline__ uint32_t s2u(const void* p) {
    return (uint32_t)__cvta_generic_to_shared(p);
}
__device__ __forceinline__ void ldsm4t(uint32_t* r, uint32_t addr) {
    asm volatile("ldmatrix.sync.aligned.m8n8.x4.trans.shared.b16 {%0,%1,%2,%3}, [%4];"
        : "=r"(r[0]), "=r"(r[1]), "=r"(r[2]), "=r"(r[3]) : "r"(addr));
}
__device__ __forceinline__ void mma_bf16(float* d, const uint32_t* a, const uint32_t* b) {
    asm volatile("mma.sync.aligned.m16n8k16.row.col.f32.bf16.bf16.f32 "
        "{%0,%1,%2,%3}, {%4,%5,%6,%7}, {%8,%9}, {%0,%1,%2,%3};"
        : "+f"(d[0]), "+f"(d[1]), "+f"(d[2]), "+f"(d[3])
        : "r"(a[0]), "r"(a[1]), "r"(a[2]), "r"(a[3]), "r"(b[0]), "r"(b[1]));
}
__device__ __forceinline__ float gatef(float a, float bb) {
    float sig = 1.f / (1.f + expf(-bb));
    float gel = 0.5f * a * (1.f + erff(a * 0.70710678118654752f));
    return a * sig + bb * gel;
}
__device__ __forceinline__ float4 bf4_to_f4(uint2 u) {
    __nv_bfloat162 p0 = *(__nv_bfloat162*)&u.x;
    __nv_bfloat162 p1 = *(__nv_bfloat162*)&u.y;
    return make_float4(__low2float(p0), __high2float(p0),
                       __low2float(p1), __high2float(p1));
}

// ---------------- prep: fold LN weights, bf16 weights, zero ss ----------------
__global__ void prep_kernel(const float* __restrict__ qkv_w,
                            const float* __restrict__ n1w, const float* __restrict__ n1b,
                            const float* __restrict__ ffn1_w, const float* __restrict__ ffn2_w,
                            const float* __restrict__ n2w, const float* __restrict__ n2b,
                            const float* __restrict__ ffn_out_w, float* __restrict__ ss) {
    int r = blockIdx.x;
    int k = threadIdx.x;  // 0..95
    __shared__ float red[96];
    if (r < 288) {
        float wv = qkv_w[r * 96 + k];
        g_Aqh[r * 96 + k] = __float2bfloat16(wv * n1w[k]);
        red[k] = wv * n1b[k];
        __syncthreads();
        if (k == 0) { float s = 0.f; for (int j = 0; j < 96; j++) s += red[j]; g_bq[r] = s; }
    } else if (r < 800) {
        int c = r - 288;                  // 0..511
        int T = c >> 4, wi = c & 15;
        int g = T * 8 + (wi & 7);
        bool valid = (g < 255);
        const float* W = (wi < 8) ? ffn1_w : ffn2_w;
        float wv = valid ? W[g * 96 + k] : 0.f;
        g_Agh[c * 96 + k] = __float2bfloat16(wv * n2w[k]);
        red[k] = wv * n2b[k];
        __syncthreads();
        if (k == 0) {
            float s = 0.f; for (int j = 0; j < 96; j++) s += red[j];
            if (valid) g_bg[(wi < 8 ? 0 : 256) + g] = s;
        }
    } else if (r < 896) {
        int o = r - 800;                  // 0..95
        for (int kk = k; kk < 256; kk += 96) {
            float v = (kk < 255) ? ffn_out_w[o * 255 + kk] : 0.f;
            g_Fh[o * 256 + kk] = __float2bfloat16(v);
        }
    } else {
        for (int j = k; j < BATCH * 204; j += 96) ss[j] = 0.f;
    }
}

// ---------------- LN1: normalize to bf16 directly (pair of pixels per thread) ----------------
__global__ void ln_norm(const float* __restrict__ x, __nv_bfloat16* __restrict__ xn) {
    long long i = (long long)blockIdx.x * blockDim.x + threadIdx.x;
    if (i >= (long long)BATCH * HW / 2) return;
    int b = (int)(i / (HW / 2));
    int pix = (int)(i % (HW / 2)) * 2;
    const float* xp = x + (long long)b * 96 * HW + pix;
    float s0 = 0.f, s1 = 0.f, q0 = 0.f, q1 = 0.f;
    #pragma unroll 8
    for (int c = 0; c < 96; c++) {
        float2 v = *(const float2*)(xp + (long long)c * HW);
        s0 += v.x; s1 += v.y; q0 += v.x * v.x; q1 += v.y * v.y;
    }
    float m0 = s0 * (1.f / 96.f), m1 = s1 * (1.f / 96.f);
    float r0 = rsqrtf(q0 * (1.f / 96.f) - m0 * m0 + 1e-5f);
    float r1 = rsqrtf(q1 * (1.f / 96.f) - m1 * m1 + 1e-5f);
    __nv_bfloat16* op = xn + (long long)b * 96 * HW + pix;
    #pragma unroll 8
    for (int c = 0; c < 96; c++) {
        float2 v = *(const float2*)(xp + (long long)c * HW);
        __nv_bfloat162 o(__float2bfloat16((v.x - m0) * r0),
                         __float2bfloat16((v.y - m1) * r1));
        *(__nv_bfloat162*)(op + (long long)c * HW) = o;
    }
}

// ---------------- tensor-core GEMM: C[M,65536]=A(bf16)[M,K]@B(bf16), 1-term MMA ----------------
// BM in {96,128}, BN=128, BK=32, NT=2*BM threads. k-major smem, trans ldmatrix.
// EPI: 0 plain(+RESID), 1 +bias, 2 dual-gate. STATS: fused LN2 -> writes normalized bf16 xno.
// OBF16: C is bf16.
template <int BM, int EPI, int RESID, int STATS, int OBF16>
__global__ __launch_bounds__(2 * BM) void gemm_t(
    const __nv_bfloat16* __restrict__ Ah,
    const __nv_bfloat16* __restrict__ B, const float* __restrict__ R, void* __restrict__ Cv,
    const float* __restrict__ bias,
    __nv_bfloat16* __restrict__ xno,
    int M, int K, int Kpad,
    long long sA, long long sB, long long sR, long long sC)
{
    constexpr int NT = 2 * BM;
    constexpr int NW = NT / 32;                    // warps: 8 or 6
    constexpr int NBJ = (32 + NW - 1) / NW;        // B k-row sweeps

    extern __shared__ __align__(16) char smem_raw[];
    __nv_bfloat16* Ash = (__nv_bfloat16*)smem_raw;       // [2][32][136]
    __nv_bfloat16* Bsh = Ash + 2 * 4352;

    Ah += (long long)blockIdx.z * sA;
    B  += (long long)blockIdx.z * sB;
    float*         Cf = (float*)Cv         + (long long)blockIdx.z * sC;
    __nv_bfloat16* Cb = (__nv_bfloat16*)Cv + (long long)blockIdx.z * sC;
    if (RESID) R += (long long)blockIdx.z * sR;
    if (STATS) xno += (long long)blockIdx.z * 96 * HW;

    const int m_base = blockIdx.y * BM;
    const int n_base = blockIdx.x * 128;
    const int tid  = threadIdx.x;
    const int lane = tid & 31;
    const int warp = tid >> 5;
    const int wm = warp >> 1, wn = warp & 1;

    // loader coords
    const int bcol = (tid & 31) * 4;   // B col (fixed per thread)
    const int bk0  = warp;             // B k-row base (+NW*j)
    const int am   = tid % BM;         // A m (fixed)
    const int akc0 = tid / BM;         // A k-chunk base (0/1), chunks akc0+2j

    float acc[2][8][4];
    #pragma unroll
    for (int i = 0; i < 2; i++)
        #pragma unroll
        for (int j = 0; j < 8; j++)
            #pragma unroll
            for (int q = 0; q < 4; q++) acc[i][j][q] = 0.f;

    const int nst = (K + 31) >> 5;
    uint4 rgah[2];
    uint2 rbex[NBJ];

    // ldmatrix lane-derived offsets
    const int a_row = (lane & 7) + ((lane >> 4) & 1) * 8;
    const int a_col = ((lane >> 3) & 1) * 8;
    const int b_row = (lane & 7) + ((lane >> 3) & 1) * 8;
    const int b_col = ((lane >> 4) & 1) * 8 + wn * 64;

    auto fetch = [&](int kg) {
        #pragma unroll
        for (int j = 0; j < 2; j++) {
            int kc = akc0 + 2 * j;
            int grow = m_base + am;
            if (grow < M) {
                long long off = (long long)grow * Kpad + kg + kc * 8;
                rgah[j] = *(const uint4*)(Ah + off);
            } else {
                rgah[j] = make_uint4(0, 0, 0, 0);
            }
        }
        #pragma unroll
        for (int j = 0; j < NBJ; j++) {
            int kr = bk0 + NW * j;
            if (kr < 32) {
                int kb = kg + kr;
                rbex[j] = (kb < K) ? *(const uint2*)(B + (long long)kb * HW + n_base + bcol)
                                   : make_uint2(0, 0);
            }
        }
    };
    auto stash = [&](int buf) {
        int base = buf * 4352;
        #pragma unroll
        for (int j = 0; j < 2; j++) {
            int kb = (akc0 + 2 * j) * 8;
            const __nv_bfloat16* ph = (const __nv_bfloat16*)&rgah[j];
            #pragma unroll
            for (int rr = 0; rr < 8; rr++)
                Ash[base + (kb + rr) * 136 + am] = ph[rr];
        }
        #pragma unroll
        for (int j = 0; j < NBJ; j++) {
            int kr = bk0 + NW * j;
            if (kr < 32)
                *(uint2*)&Bsh[base + kr * 136 + bcol] = rbex[j];
        }
    };

    fetch(0);
    stash(0);
    __syncthreads();

    for (int s = 0; s < nst; s++) {
        int buf = s & 1;
        if (s + 1 < nst) fetch((s + 1) * 32);

        int base = buf * 4352;
        #pragma unroll
        for (int step = 0; step < 2; step++) {
            int k0 = step * 16;
            uint32_t ah[2][4];
            #pragma unroll
            for (int i = 0; i < 2; i++) {
                int col = wm * 32 + i * 16 + a_col;
                int off = base + (k0 + a_row) * 136 + col;
                ldsm4t(ah[i], s2u(&Ash[off]));
            }
            uint32_t bh[4][4];
            #pragma unroll
            for (int jp = 0; jp < 4; jp++) {
                int col = b_col + jp * 16;
                int off = base + (k0 + b_row) * 136 + col;
                ldsm4t(bh[jp], s2u(&Bsh[off]));
            }
            #pragma unroll
            for (int i = 0; i < 2; i++) {
                #pragma unroll
                for (int j = 0; j < 8; j++) {
                    int jp = j >> 1;
                    const uint32_t* bhp = (j & 1) ? bh[jp] + 2 : bh[jp];
                    mma_bf16(acc[i][j], ah[i], bhp);
                }
            }
        }
        if (s + 1 < nst) stash(buf ^ 1);
        __syncthreads();
    }

    // ---------------- epilogue ----------------
    float ls[16], ls2[16];
    if (STATS) {
        #pragma unroll
        for (int e = 0; e < 16; e++) { ls[e] = 0.f; ls2[e] = 0.f; }
    }

    if (EPI == 2) {
        #pragma unroll
        for (int i = 0; i < 2; i++) {
            int T = (m_base >> 4) + wm * 2 + i;
            int g = T * 8 + (lane >> 2);
            if (g < 255) {
                float b1 = bias[g], b2 = bias[256 + g];
                #pragma unroll
                for (int j = 0; j < 8; j++) {
                    int col = n_base + wn * 64 + j * 8 + 2 * (lane & 3);
                    float vx = gatef(acc[i][j][0] + b1, acc[i][j][2] + b2);
                    float vy = gatef(acc[i][j][1] + b1, acc[i][j][3] + b2);
                    if (OBF16) {
                        __nv_bfloat162 bv2(__float2bfloat16(vx), __float2bfloat16(vy));
                        *(__nv_bfloat162*)(Cb + (long long)g * HW + col) = bv2;
                    } else {
                        *(float2*)(Cf + (long long)g * HW + col) = make_float2(vx, vy);
                    }
                }
            }
        }
    } else {
        #pragma unroll
        for (int i = 0; i < 2; i++) {
            int r0 = m_base + wm * 32 + i * 16 + (lane >> 2);
            int r1 = r0 + 8;
            float bv0 = 0.f, bv1 = 0.f;
            if (EPI == 1) {
                if (r0 < M) bv0 = bias[r0];
                if (r1 < M) bv1 = bias[r1];
            }
            #pragma unroll
            for (int j = 0; j < 8; j++) {
                int col = n_base + wn * 64 + j * 8 + 2 * (lane & 3);
                #pragma unroll
                for (int half = 0; half < 2; half++) {
                    int rr = half ? r1 : r0;
                    if (rr >= M) continue;
                    float bv = half ? bv1 : bv0;
                    float vx = acc[i][j][half * 2 + 0] + bv;
                    float vy = acc[i][j][half * 2 + 1] + bv;
                    long long o = (long long)rr * HW + col;
                    if (RESID) {
                        float2 rv = *(const float2*)(R + o);
                        vx += rv.x; vy += rv.y;
                    }
                    if (OBF16) {
                        __nv_bfloat162 bv2(__float2bfloat16(vx), __float2bfloat16(vy));
                        *(__nv_bfloat162*)(Cb + o) = bv2;
                    } else {
                        *(float2*)(Cf + o) = make_float2(vx, vy);
                    }
                    if (STATS) {
                        acc[i][j][half * 2 + 0] = vx;   // retain final values
                        acc[i][j][half * 2 + 1] = vy;
                        ls[2 * j] += vx; ls[2 * j + 1] += vy;
                        ls2[2 * j] += vx * vx; ls2[2 * j + 1] += vy * vy;
                    }
                }
            }
        }
    }

    if (STATS) {
        __syncthreads();
        float* sstat = (float*)smem_raw;   // [0..127]=sum->mu, [128..255]=sumsq->rstd
        for (int t = tid; t < 256; t += NT) sstat[t] = 0.f;
        __syncthreads();
        if (wm < 3) {
            #pragma unroll
            for (int o = 16; o >= 4; o >>= 1) {
                #pragma unroll
                for (int e = 0; e < 16; e++) {
                    ls[e]  += __shfl_down_sync(0xffffffffu, ls[e],  o);
                    ls2[e] += __shfl_down_sync(0xffffffffu, ls2[e], o);
                }
            }
            if (lane < 4) {
                #pragma unroll
                for (int e = 0; e < 16; e++) {
                    int j = e >> 1, q = e & 1;
                    int nl = wn * 64 + j * 8 + 2 * lane + q;
                    atomicAdd(&sstat[nl], ls[e]);
                    atomicAdd(&sstat[128 + nl], ls2[e]);
                }
            }
        }
        __syncthreads();
        if (tid < 128) {
            float sm = sstat[tid] * (1.f / 96.f);
            float sq = sstat[tid + 128] * (1.f / 96.f);
            sstat[tid] = sm;
            sstat[tid + 128] = rsqrtf(sq - sm * sm + 1e-5f);
        }
        __syncthreads();
        #pragma unroll
        for (int i = 0; i < 2; i++) {
            int r0 = m_base + wm * 32 + i * 16 + (lane >> 2);
            #pragma unroll
            for (int j = 0; j < 8; j++) {
                int col128 = wn * 64 + j * 8 + 2 * (lane & 3);
                float mu0 = sstat[col128],       mu1 = sstat[col128 + 1];
                float rs0 = sstat[128 + col128], rs1 = sstat[129 + col128];
                #pragma unroll
                for (int half = 0; half < 2; half++) {
                    int rr = half ? (r0 + 8) : r0;
                    if (rr >= M) continue;
                    float vx = acc[i][j][half * 2 + 0];
                    float vy = acc[i][j][half * 2 + 1];
                    __nv_bfloat162 o2(__float2bfloat16((vx - mu0) * rs0),
                                      __float2bfloat16((vy - mu1) * rs1));
                    *(__nv_bfloat162*)(xno + (long long)rr * HW + n_base + col128) = o2;
                }
            }
        }
    }
}

// ---------------- 3x3 depthwise conv: 32x32 tile, bf16 in / bf16 out ----------------
__global__ __launch_bounds__(256) void dwconv3(const __nv_bfloat16* __restrict__ in,
                                               const float* __restrict__ w,
                                               __nv_bfloat16* __restrict__ out) {
    int zc = blockIdx.z;
    int c = zc % 288;
    const __nv_bfloat16* src = in + (long long)zc * HW;
    __nv_bfloat16* dst = out + (long long)zc * HW;
    int ox = blockIdx.x * 32, oy = blockIdx.y * 32;
    __shared__ float s[34][40];
    int tid = threadIdx.x;
    #pragma unroll
    for (int j = 0; j < 2; j++) {
        int sl = tid + j * 256;
        if (sl < 340) {
            int r = sl / 10, q = sl - r * 10;
            int gy = oy + r - 1, gx = ox - 4 + q * 4;
            float4 v = make_float4(0.f, 0.f, 0.f, 0.f);
            if (gy >= 0 && gy < 256 && gx >= 0 && gx <= 252) {
                uint2 u = *(const uint2*)(src + gy * 256 + gx);
                v = bf4_to_f4(u);
            }
            *(float4*)&s[r][q * 4] = v;
        }
    }
    __syncthreads();
    const float* wc = w + c * 9;
    float w00 = wc[0], w01 = wc[1], w02 = wc[2];
    float w10 = wc[3], w11 = wc[4], w12 = wc[5];
    float w20 = wc[6], w21 = wc[7], w22 = wc[8];
    int row  = tid >> 3;
    int colq = (tid & 7) * 4;
    float v[3][6];
    #pragma unroll
    for (int dr = 0; dr < 3; dr++) {
        float4 m = *(const float4*)&s[row + dr][colq + 4];
        v[dr][0] = s[row + dr][colq + 3];
        v[dr][1] = m.x; v[dr][2] = m.y; v[dr][3] = m.z; v[dr][4] = m.w;
        v[dr][5] = s[row + dr][colq + 8];
    }
    float o[4];
    #pragma unroll
    for (int t = 0; t < 4; t++) {
        o[t] = w00 * v[0][t] + w01 * v[0][t + 1] + w02 * v[0][t + 2]
             + w10 * v[1][t] + w11 * v[1][t + 1] + w12 * v[1][t + 2]
             + w20 * v[2][t] + w21 * v[2][t + 1] + w22 * v[2][t + 2];
    }
    __nv_bfloat162 p0(__float2bfloat16(o[0]), __float2bfloat16(o[1]));
    __nv_bfloat162 p1(__float2bfloat16(o[2]), __float2bfloat16(o[3]));
    uint2 u;
    u.x = *(uint32_t*)&p0; u.y = *(uint32_t*)&p1;
    *(uint2*)(dst + (oy + row) * 256 + ox + colq) = u;
}

// ---------------- svp 1x1 conv -> bf16 ----------------
__global__ void svp_kernel(const float* __restrict__ fea, const float* __restrict__ w,
                           __nv_bfloat16* __restrict__ out) {
    int i = blockIdx.x * blockDim.x + threadIdx.x;
    if (i >= BATCH * HW) return;
    int b = i >> 16, pix = i & 65535;
    const float* f = fea + (long long)b * 3 * HW + pix;
    float f0 = f[0], f1 = f[HW], f2 = f[2 * HW];
    __nv_bfloat16* o = out + (long long)b * 12 * HW + pix;
    #pragma unroll
    for (int r = 0; r < 12; r++)
        o[(long long)r * HW] = __float2bfloat16(w[r * 3] * f0 + w[r * 3 + 1] * f1 + w[r * 3 + 2] * f2);
}

// ---------------- Gram partials + fused per-row sum of squares ----------------
__global__ __launch_bounds__(672) void gram_kernel(const __nv_bfloat16* __restrict__ qkvd,
                                                   const __nv_bfloat16* __restrict__ svpq,
                                                   float* __restrict__ gp,
                                                   float* __restrict__ ss) {
    __shared__ float qs[27 * GPAD];
    __shared__ float ks[24 * GPAD];
    __shared__ float red_s[51];
    int seg = blockIdx.x;
    int bh  = blockIdx.y;
    int b = bh >> 2, h = bh & 3;
    int tid = threadIdx.x;
    int c = tid / 24, d = tid % 24;
    bool active = tid < 648;
    long long segoff = (long long)seg * (HW / NSEG);
    float acc = 0.f;
    float sqacc[3] = {0.f, 0.f, 0.f};
    if (tid < 51) red_s[tid] = 0.f;

    for (int ch = 0; ch < HW / NSEG; ch += GCH) {
        int jj = 0;
        for (int i = tid; i < 51 * (GCH / 4); i += 672, jj++) {
            int row = i / (GCH / 4), col4 = i % (GCH / 4);
            const __nv_bfloat16* src;
            float* dstb;
            if (row < 27) {
                src = (row < 24) ? qkvd + ((long long)b * 288 + h * 24 + row) * HW
                                 : svpq + ((long long)b * 12 + h * 3 + (row - 24)) * HW;
                dstb = qs + row * GPAD;
            } else {
                int rr = row - 27;
                src = qkvd + ((long long)b * 288 + 96 + h * 24 + rr) * HW;
                dstb = ks + rr * GPAD;
            }
            float4 v = bf4_to_f4(*(const uint2*)(src + segoff + ch + col4 * 4));
            *(float4*)(dstb + col4 * 4) = v;
            sqacc[jj] += v.x * v.x + v.y * v.y + v.z * v.z + v.w * v.w;
        }
        __syncthreads();
        if (active) {
            const float4* q4 = (const float4*)(qs + c * GPAD);
            const float4* k4 = (const float4*)(ks + d * GPAD);
            #pragma unroll 8
            for (int p = 0; p < GCH / 4; p++) {
                float4 qv = q4[p], kv = k4[p];
                acc += qv.x * kv.x + qv.y * kv.y + qv.z * kv.z + qv.w * kv.w;
            }
        }
        __syncthreads();
    }
    if (active) gp[((long long)seg * 16 + bh) * 648 + tid] = acc;

    {
        int jj = 0;
        for (int i = tid; i < 51 * (GCH / 4); i += 672, jj++) {
            int row = i / (GCH / 4);
            atomicAdd(&red_s[row], sqacc[jj]);
        }
    }
    __syncthreads();
    if (tid < 51) {
        int row = tid;
        int idx;
        if (row < 24)       idx = b * 204 + h * 24 + row;
        else if (row < 27)  idx = b * 204 + 192 + h * 3 + (row - 24);
        else                idx = b * 204 + 96 + h * 24 + (row - 27);
        atomicAdd(&ss[idx], red_s[row]);
    }
}

// ---------------- attn softmax + fold proj_out -> M[b] (bf16) ----------------
__global__ void attnm_kernel(const float* __restrict__ gp, const float* __restrict__ ss,
                             const float* __restrict__ temp, const float* __restrict__ projw,
                             __nv_bfloat16* __restrict__ Mh) {
    int b = blockIdx.x;
    __shared__ float attn_s[4][27][24];
    int tid = threadIdx.x;
    if (tid < 108) {
        int h = tid / 27, c = tid % 27;
        float ssq = (c < 24) ? ss[b * 204 + h * 24 + c]
                             : ss[b * 204 + 192 + h * 3 + (c - 24)];
        float nq = fmaxf(sqrtf(ssq), 1e-12f);
        float t = temp[h];
        float row[24];
        #pragma unroll
        for (int d = 0; d < 24; d++) {
            float g = 0.f;
            for (int s = 0; s < NSEG; s++)
                g += gp[((long long)s * 16 + b * 4 + h) * 648 + c * 24 + d];
            float nk = fmaxf(sqrtf(ss[b * 204 + 96 + h * 24 + d]), 1e-12f);
            row[d] = g * t / (nq * nk);
        }
        float mx = row[0];
        #pragma unroll
        for (int d = 1; d < 24; d++) mx = fmaxf(mx, row[d]);
        float sum = 0.f;
        #pragma unroll
        for (int d = 0; d < 24; d++) { row[d] = expf(row[d] - mx); sum += row[d]; }
        float inv = 1.f / sum;
        #pragma unroll
        for (int d = 0; d < 24; d++) attn_s[h][c][d] = row[d] * inv;
    }
    __syncthreads();
    for (int e = tid; e < 96 * 96; e += blockDim.x) {
        int o = e / 96, col = e % 96;
        int h = col / 24, d = col % 24;
        float s = 0.f;
        #pragma unroll
        for (int c = 0; c < 27; c++)
            s += projw[o * 108 + h * 27 + c] * attn_s[h][c][d];
        Mh[b * 9216 + e] = __float2bfloat16(s);
    }
}

// ---------------- launch ----------------
extern "C" void kernel_launch(void* const* d_in, const int* in_sizes, int n_in,
                              void* d_out, int out_size) {
    const float* x           = (const float*)d_in[0];
    const float* svp_fea     = (const float*)d_in[1];
    const float* n1w         = (const float*)d_in[2];
    const float* n1b         = (const float*)d_in[3];
    const float* qkv_w       = (const float*)d_in[4];
    const float* qkv_dw_w    = (const float*)d_in[5];
    const float* svp_w       = (const float*)d_in[6];
    const float* temperature = (const float*)d_in[7];
    const float* proj_out_w  = (const float*)d_in[8];
    const float* n2w         = (const float*)d_in[9];
    const float* n2b         = (const float*)d_in[10];
    const float* ffn1_w      = (const float*)d_in[11];
    const float* ffn2_w      = (const float*)d_in[12];
    const float* ffn_out_w   = (const float*)d_in[13];
    float* out = (float*)d_out;

    float *ss, *gp, *bq, *bg;
    __nv_bfloat16 *qkv, *qkvd, *x2n, *svpq, *Mh, *Aqh, *Agh, *Fh;
    cudaGetSymbolAddress((void**)&qkv,  g_qkv);
    cudaGetSymbolAddress((void**)&qkvd, g_qkvd);
    cudaGetSymbolAddress((void**)&x2n,  g_x2n);
    cudaGetSymbolAddress((void**)&svpq, g_svpq);
    cudaGetSymbolAddress((void**)&ss,   g_ss);
    cudaGetSymbolAddress((void**)&gp,   g_gp);
    cudaGetSymbolAddress((void**)&Mh,   g_Mh);
    cudaGetSymbolAddress((void**)&Aqh,  g_Aqh);
    cudaGetSymbolAddress((void**)&bq,   g_bq);
    cudaGetSymbolAddress((void**)&Agh,  g_Agh);
    cudaGetSymbolAddress((void**)&bg,   g_bg);
    cudaGetSymbolAddress((void**)&Fh,   g_Fh);

    // xn (LN1 output) aliases qkvd: consumed by gemm2 before dwconv3 writes qkvd.
    __nv_bfloat16* xn = qkvd;

    const int GEMM_SMEM = 2 * 2 * 32 * 136 * 2;   // 34816 bytes (A + B only)
    cudaFuncSetAttribute(gemm_t<96, 1, 0, 0, 1>, cudaFuncAttributeMaxDynamicSharedMemorySize, GEMM_SMEM);
    cudaFuncSetAttribute(gemm_t<96, 0, 1, 1, 0>, cudaFuncAttributeMaxDynamicSharedMemorySize, GEMM_SMEM);
    cudaFuncSetAttribute(gemm_t<128, 2, 0, 0, 1>, cudaFuncAttributeMaxDynamicSharedMemorySize, GEMM_SMEM);
    cudaFuncSetAttribute(gemm_t<96, 0, 1, 0, 0>, cudaFuncAttributeMaxDynamicSharedMemorySize, GEMM_SMEM);

    const int pixBlocks = (BATCH * HW + 255) / 256;

    // 0. fold LN weights into bf16 A matrices; zero ss
    prep_kernel<<<897, 96>>>(qkv_w, n1w, n1b, ffn1_w, ffn2_w, n2w, n2b, ffn_out_w, ss);
    // 1. LN1 -> normalized bf16 xn
    ln_norm<<<(BATCH * HW / 2 + 255) / 256, 256>>>(x, xn);
    // 2. qkv = Aq @ xn + bq -> bf16
    gemm_t<96, 1, 0, 0, 1><<<dim3(512, 3, BATCH), 192, GEMM_SMEM>>>(Aqh, xn, nullptr, qkv,
        bq, nullptr, 288, 96, 96, 0, 96LL * HW, 0, 288LL * HW);
    // 3. depthwise 3x3 (bf16 in, bf16 out) — overwrites qkvd (xn dead)
    dwconv3<<<dim3(8, 8, BATCH * 288), 256>>>(qkv, qkv_dw_w, qkvd);
    // 4. svp_q -> bf16
    svp_kernel<<<pixBlocks, 256>>>(svp_fea, svp_w, svpq);
    // 5. Gram partials + fused sumsq (all bf16 inputs)
    gram_kernel<<<dim3(NSEG, 16), 672>>>(qkvd, svpq, gp, ss);
    // 6. softmax + fold proj_out -> M[b] bf16
    attnm_kernel<<<BATCH, 128>>>(gp, ss, temperature, proj_out_w, Mh);
    // 7. x2 = x + M_b @ v -> out (fp32) + fused LN2 -> x2n bf16
    gemm_t<96, 0, 1, 1, 0><<<dim3(512, 1, BATCH), 192, GEMM_SMEM>>>(Mh, qkvd + 192LL * HW, x, out,
        nullptr, x2n, 96, 96, 96, 9216, 288LL * HW, 96LL * HW, 96LL * HW);
    // 8. interleaved ffn1/ffn2 GEMM on x2n + fused dual-gate -> g (bf16)
    gemm_t<128, 2, 0, 0, 1><<<dim3(512, 4, BATCH), 256, GEMM_SMEM>>>(Agh, x2n, nullptr, qkv,
        bg, nullptr, 512, 96, 96, 0, 96LL * HW, 0, 288LL * HW);
    // 9. out = out + ffn_out_w @ g
    gemm_t<96, 0, 1, 0, 0><<<dim3(512, 1, BATCH), 192, GEMM_SMEM>>>(Fh, qkv, out, out,
        nullptr, nullptr, 96, 255, 256, 0, 288LL * HW, 96LL * HW, 96LL * HW);
}